// round 8
// baseline (speedup 1.0000x reference)
#include <cuda_runtime.h>
#include <math.h>
#include <stdint.h>

typedef unsigned long long u64;

// Problem constants
constexpr int D     = 768;
constexpr int SQ    = 2048;
constexpr int BATCH = 4;
constexpr int NH    = 12;
constexpr int HDIM  = 64;
constexpr int MTOT  = BATCH * SQ;   // 8192 rows

// Scratch (alloc-free rule: __device__ globals)
__device__ float g_Q[MTOT * D];
__device__ float g_K[MTOT * D];
__device__ float g_V[MTOT * D];
__device__ float g_ctx[MTOT * D];

// ---- packed f32x2 helpers ------------------------------------------------
__device__ __forceinline__ u64 splat2(float x) {
    u64 r; unsigned xi = __float_as_uint(x);
    asm("mov.b64 %0, {%1, %1};" : "=l"(r) : "r"(xi));
    return r;
}
__device__ __forceinline__ void ffma2(u64 &d, u64 a, u64 b) {
    asm("fma.rn.f32x2 %0, %1, %2, %0;" : "+l"(d) : "l"(a), "l"(b));
}
__device__ __forceinline__ u64 fmul2(u64 a, u64 b) {
    u64 r; asm("mul.rn.f32x2 %0, %1, %2;" : "=l"(r) : "l"(a), "l"(b));
    return r;
}
__device__ __forceinline__ float2 unpack2(u64 v) {
    float2 f;
    asm("mov.b64 {%0, %1}, %2;" : "=f"(f.x), "=f"(f.y) : "l"(v));
    return f;
}
__device__ __forceinline__ u64 dtou(double d) { return __double_as_longlong(d); }

// ---------------------------------------------------------------------------
// GEMM (R3, measured 78% of f32x2 peak): C[m][n] = sum_k A[m][k]*W[n][k]+b[n]
// BM=BN=128, BK=16, 256 threads, 8 rows (4 pairs) x 8 cols per thread.
// ---------------------------------------------------------------------------
constexpr int BM = 128, BN = 128, BK = 16, BMP = 132;

__device__ __forceinline__ void gemm_nt(const float* __restrict__ A,
                                        const float* __restrict__ W,
                                        const float* __restrict__ bias,
                                        float* __restrict__ C) {
    __shared__ __align__(16) float As[BK][BMP];   // [k][m]
    __shared__ __align__(16) float Bs[BK][BMP];   // [k][n]
    const int tid = threadIdx.x;
    const int tx = tid & 15, ty = tid >> 4;
    const int m0 = blockIdx.y * BM, n0 = blockIdx.x * BN;
    const int lm = tid >> 1;          // 0..127
    const int lk = (tid & 1) * 8;     // 0 or 8
    const float* Ap = A + (size_t)(m0 + lm) * D + lk;
    const float* Wp = W + (size_t)(n0 + lm) * D + lk;

    u64 acc[4][8];
#pragma unroll
    for (int i = 0; i < 4; i++)
#pragma unroll
        for (int j = 0; j < 8; j++) acc[i][j] = 0ull;

    float4 ra0 = *(const float4*)(Ap);
    float4 ra1 = *(const float4*)(Ap + 4);
    float4 rb0 = *(const float4*)(Wp);
    float4 rb1 = *(const float4*)(Wp + 4);

    for (int kt = 0; kt < D; kt += BK) {
        As[lk + 0][lm] = ra0.x; As[lk + 1][lm] = ra0.y;
        As[lk + 2][lm] = ra0.z; As[lk + 3][lm] = ra0.w;
        As[lk + 4][lm] = ra1.x; As[lk + 5][lm] = ra1.y;
        As[lk + 6][lm] = ra1.z; As[lk + 7][lm] = ra1.w;
        Bs[lk + 0][lm] = rb0.x; Bs[lk + 1][lm] = rb0.y;
        Bs[lk + 2][lm] = rb0.z; Bs[lk + 3][lm] = rb0.w;
        Bs[lk + 4][lm] = rb1.x; Bs[lk + 5][lm] = rb1.y;
        Bs[lk + 6][lm] = rb1.z; Bs[lk + 7][lm] = rb1.w;
        __syncthreads();
        if (kt + BK < D) {   // prefetch next tile
            ra0 = *(const float4*)(Ap + kt + BK);
            ra1 = *(const float4*)(Ap + kt + BK + 4);
            rb0 = *(const float4*)(Wp + kt + BK);
            rb1 = *(const float4*)(Wp + kt + BK + 4);
        }
#pragma unroll
        for (int kk = 0; kk < BK; kk++) {
            double2 A0 = *(const double2*)&As[kk][ty * 8];
            double2 A1 = *(const double2*)&As[kk][ty * 8 + 4];
            float4 B0 = *(const float4*)&Bs[kk][tx * 4];
            float4 B1 = *(const float4*)&Bs[kk][64 + tx * 4];
            u64 a[4] = {dtou(A0.x), dtou(A0.y), dtou(A1.x), dtou(A1.y)};
            u64 b[8] = {splat2(B0.x), splat2(B0.y), splat2(B0.z), splat2(B0.w),
                        splat2(B1.x), splat2(B1.y), splat2(B1.z), splat2(B1.w)};
#pragma unroll
            for (int i = 0; i < 4; i++)
#pragma unroll
                for (int j = 0; j < 8; j++)
                    ffma2(acc[i][j], a[i], b[j]);
        }
        __syncthreads();
    }

    float bb[8];
#pragma unroll
    for (int j = 0; j < 4; j++) bb[j] = bias[n0 + tx * 4 + j];
#pragma unroll
    for (int j = 0; j < 4; j++) bb[4 + j] = bias[n0 + 64 + tx * 4 + j];

#pragma unroll
    for (int i2 = 0; i2 < 4; i2++) {
        float lo[8], hi[8];
#pragma unroll
        for (int j = 0; j < 8; j++) {
            float2 v = unpack2(acc[i2][j]);
            lo[j] = v.x + bb[j];
            hi[j] = v.y + bb[j];
        }
        float* r0 = C + (size_t)(m0 + ty * 8 + 2 * i2) * D + n0;
        float* r1 = r0 + D;
        *(float4*)(r0 + tx * 4)      = make_float4(lo[0], lo[1], lo[2], lo[3]);
        *(float4*)(r0 + 64 + tx * 4) = make_float4(lo[4], lo[5], lo[6], lo[7]);
        *(float4*)(r1 + tx * 4)      = make_float4(hi[0], hi[1], hi[2], hi[3]);
        *(float4*)(r1 + 64 + tx * 4) = make_float4(hi[4], hi[5], hi[6], hi[7]);
    }
}

__global__ void __launch_bounds__(256, 2)
qkv_gemm(const float* __restrict__ x,
         const float* __restrict__ Wq, const float* __restrict__ bq,
         const float* __restrict__ Wk, const float* __restrict__ bk,
         const float* __restrict__ Wv, const float* __restrict__ bv) {
    const float* W; const float* bias; float* C;
    if (blockIdx.z == 0)      { W = Wq; bias = bq; C = g_Q; }
    else if (blockIdx.z == 1) { W = Wk; bias = bk; C = g_K; }
    else                      { W = Wv; bias = bv; C = g_V; }
    gemm_nt(x, W, bias, C);
}

__global__ void __launch_bounds__(256, 2)
out_gemm(const float* __restrict__ Wo, const float* __restrict__ bo,
         float* __restrict__ out) {
    gemm_nt(g_ctx, Wo, bo, out);
}

// ---------------------------------------------------------------------------
// Flash attention with f32x2 math, no smem growth (104 KB).
// grid (16 q-tiles, 48 bh), 256 threads. 128 q-rows/block, 64 kv/iter.
// Phase A: 8 rows (pairs) x 4 cols per thread  (ty, tx mapping)
// Phase C: 4 rows x 8 cols (pairs) per thread  (rg, cg mapping)
// ---------------------------------------------------------------------------
constexpr int QP = 132;
constexpr int KP = 68;
constexpr int SP = 68;
constexpr int ATTN_SMEM_FLOATS = 64 * QP + 64 * KP + 64 * KP + 128 * SP + 256;
constexpr int ATTN_SMEM_BYTES  = ATTN_SMEM_FLOATS * 4;   // 104448 B

__global__ void __launch_bounds__(256)
attn_kernel() {
    extern __shared__ __align__(16) float sm[];
    float* Qs = sm;                    // [d][r] d-major
    float* Ks = Qs + 64 * QP;          // [d][c] d-major
    float* Vs = Ks + 64 * KP;          // [j][d] row-major
    float* Ss = Vs + 64 * KP;          // [r][c] scores then probs
    float* alpha_s = Ss + 128 * SP;    // [128]
    float* l_s     = alpha_s + 128;    // [128]

    const int tid = threadIdx.x;
    const int tx = tid & 15, ty = tid >> 4;      // Phase A mapping
    const int rg = tid >> 3, cg = tid & 7;       // Phase C mapping
    const int bh = blockIdx.y;
    const int b = bh / NH, h = bh % NH;
    const int q0 = blockIdx.x * 128;

    const float* Qb = g_Q + (size_t)(b * SQ) * D + h * HDIM;
    const float* Kb = g_K + (size_t)(b * SQ) * D + h * HDIM;
    const float* Vb = g_V + (size_t)(b * SQ) * D + h * HDIM;

    // Load Q tile (128 x 64) transposed to d-major, scale folded in
    {
        const int lr = tid >> 1;
        const int ld0 = (tid & 1) * 32;
        const float* qrow = Qb + (size_t)(q0 + lr) * D + ld0;
#pragma unroll
        for (int i4 = 0; i4 < 8; i4++) {
            float4 v = *(const float4*)(qrow + i4 * 4);
            int d = ld0 + i4 * 4;
            Qs[(d + 0) * QP + lr] = v.x * 0.125f;
            Qs[(d + 1) * QP + lr] = v.y * 0.125f;
            Qs[(d + 2) * QP + lr] = v.z * 0.125f;
            Qs[(d + 3) * QP + lr] = v.w * 0.125f;
        }
    }

    float m_team = -INFINITY, l_team = 0.0f;   // per-row state (row = tid>>1)
    u64 accc[4][4];                             // Phase C: 4 rows x 4 col-pairs
#pragma unroll
    for (int i = 0; i < 4; i++)
#pragma unroll
        for (int j = 0; j < 4; j++) accc[i][j] = 0ull;
    __syncthreads();

    for (int kt = 0; kt < SQ; kt += 64) {
        // Load K (d-major) and V (row-major): 64 rows x 64 d
        {
            const int lr = tid >> 2;
            const int ld0 = (tid & 3) * 16;
            const float* krow = Kb + (size_t)(kt + lr) * D + ld0;
            const float* vrow = Vb + (size_t)(kt + lr) * D + ld0;
#pragma unroll
            for (int i4 = 0; i4 < 4; i4++) {
                float4 kv = *(const float4*)(krow + i4 * 4);
                int d = ld0 + i4 * 4;
                Ks[(d + 0) * KP + lr] = kv.x;
                Ks[(d + 1) * KP + lr] = kv.y;
                Ks[(d + 2) * KP + lr] = kv.z;
                Ks[(d + 3) * KP + lr] = kv.w;
                float4 vv = *(const float4*)(vrow + i4 * 4);
                *(float4*)&Vs[lr * KP + ld0 + i4 * 4] = vv;
            }
        }
        __syncthreads();

        // Phase A: S = (Q*scale) @ K^T   rows packed in pairs (f32x2)
        {
            u64 s[4][4];
#pragma unroll
            for (int i = 0; i < 4; i++)
#pragma unroll
                for (int j = 0; j < 4; j++) s[i][j] = 0ull;
#pragma unroll
            for (int d = 0; d < 64; d++) {
                double2 A0 = *(const double2*)&Qs[d * QP + ty * 8];
                double2 A1 = *(const double2*)&Qs[d * QP + ty * 8 + 4];
                float4 kv = *(const float4*)&Ks[d * KP + tx * 4];
                u64 a[4] = {dtou(A0.x), dtou(A0.y), dtou(A1.x), dtou(A1.y)};
                u64 bj[4] = {splat2(kv.x), splat2(kv.y), splat2(kv.z), splat2(kv.w)};
#pragma unroll
                for (int i = 0; i < 4; i++)
#pragma unroll
                    for (int j = 0; j < 4; j++)
                        ffma2(s[i][j], a[i], bj[j]);
            }
#pragma unroll
            for (int i2 = 0; i2 < 4; i2++) {
                float2 v0 = unpack2(s[i2][0]);
                float2 v1 = unpack2(s[i2][1]);
                float2 v2 = unpack2(s[i2][2]);
                float2 v3 = unpack2(s[i2][3]);
                *(float4*)&Ss[(ty * 8 + 2 * i2) * SP + tx * 4] =
                    make_float4(v0.x, v1.x, v2.x, v3.x);
                *(float4*)&Ss[(ty * 8 + 2 * i2 + 1) * SP + tx * 4] =
                    make_float4(v0.y, v1.y, v2.y, v3.y);
            }
        }
        __syncthreads();

        // Online softmax: row r = tid>>1, half = tid&1 handles 32 cols (in place)
        {
            const int r = tid >> 1, half = tid & 1;
            float* base = &Ss[r * SP + half * 32];
            float p[32];
            float mloc = -INFINITY;
#pragma unroll
            for (int i4 = 0; i4 < 8; i4++) {
                float4 sv = *(const float4*)(base + i4 * 4);
                p[i4 * 4 + 0] = sv.x; p[i4 * 4 + 1] = sv.y;
                p[i4 * 4 + 2] = sv.z; p[i4 * 4 + 3] = sv.w;
                mloc = fmaxf(mloc, fmaxf(fmaxf(sv.x, sv.y), fmaxf(sv.z, sv.w)));
            }
            mloc = fmaxf(mloc, __shfl_xor_sync(0xffffffffu, mloc, 1));
            float m_new = fmaxf(m_team, mloc);
            float alpha = __expf(m_team - m_new);
            float lsum = 0.0f;
#pragma unroll
            for (int i = 0; i < 32; i++) {
                p[i] = __expf(p[i] - m_new);
                lsum += p[i];
            }
            lsum += __shfl_xor_sync(0xffffffffu, lsum, 1);
            l_team = l_team * alpha + lsum;
            m_team = m_new;
#pragma unroll
            for (int i4 = 0; i4 < 8; i4++)
                *(float4*)(base + i4 * 4) =
                    make_float4(p[i4 * 4 + 0], p[i4 * 4 + 1],
                                p[i4 * 4 + 2], p[i4 * 4 + 3]);
            if (half == 0) alpha_s[r] = alpha;
        }
        __syncthreads();

        // Phase C: O = O*alpha + P @ V   (4 rows x 8 cols, cols packed, f32x2)
        {
#pragma unroll
            for (int i = 0; i < 4; i++) {
                u64 al = splat2(alpha_s[rg * 4 + i]);
#pragma unroll
                for (int j = 0; j < 4; j++)
                    accc[i][j] = fmul2(accc[i][j], al);
            }
#pragma unroll
            for (int k = 0; k < 64; k++) {
                double2 v01 = *(const double2*)&Vs[k * KP + cg * 8];
                double2 v23 = *(const double2*)&Vs[k * KP + cg * 8 + 4];
                u64 v[4] = {dtou(v01.x), dtou(v01.y), dtou(v23.x), dtou(v23.y)};
#pragma unroll
                for (int i = 0; i < 4; i++) {
                    u64 pp = splat2(Ss[(rg * 4 + i) * SP + k]);
                    ffma2(accc[i][0], pp, v[0]);
                    ffma2(accc[i][1], pp, v[1]);
                    ffma2(accc[i][2], pp, v[2]);
                    ffma2(accc[i][3], pp, v[3]);
                }
            }
        }
        __syncthreads();   // protect tiles for next iteration
    }

    // Final normalize + store ([b,s,h*64+d] layout for the O-projection)
    if ((tid & 1) == 0) l_s[tid >> 1] = l_team;
    __syncthreads();
    float* Ob = g_ctx + (size_t)(b * SQ + q0) * D + h * HDIM;
#pragma unroll
    for (int i = 0; i < 4; i++) {
        float inv = 1.0f / l_s[rg * 4 + i];
        float2 o0 = unpack2(accc[i][0]);
        float2 o1 = unpack2(accc[i][1]);
        float2 o2 = unpack2(accc[i][2]);
        float2 o3 = unpack2(accc[i][3]);
        float* orow = Ob + (size_t)(rg * 4 + i) * D + cg * 8;
        *(float4*)(orow)     = make_float4(o0.x * inv, o0.y * inv,
                                           o1.x * inv, o1.y * inv);
        *(float4*)(orow + 4) = make_float4(o2.x * inv, o2.y * inv,
                                           o3.x * inv, o3.y * inv);
    }
}

// ---------------------------------------------------------------------------
extern "C" void kernel_launch(void* const* d_in, const int* in_sizes, int n_in,
                              void* d_out, int out_size) {
    const float* x    = (const float*)d_in[0];
    const float* QW_w = (const float*)d_in[1];
    const float* QW_b = (const float*)d_in[2];
    const float* KW_w = (const float*)d_in[3];
    const float* KW_b = (const float*)d_in[4];
    const float* VW_w = (const float*)d_in[5];
    const float* VW_b = (const float*)d_in[6];
    const float* OW_w = (const float*)d_in[7];
    const float* OW_b = (const float*)d_in[8];
    float* out = (float*)d_out;

    cudaFuncSetAttribute(attn_kernel,
                         cudaFuncAttributeMaxDynamicSharedMemorySize,
                         ATTN_SMEM_BYTES);

    dim3 gq(D / BN, MTOT / BM, 3);     // (6, 64, 3)
    qkv_gemm<<<gq, 256>>>(x, QW_w, QW_b, KW_w, KW_b, VW_w, VW_b);

    dim3 ga(SQ / 128, BATCH * NH);     // (16, 48)
    attn_kernel<<<ga, 256, ATTN_SMEM_BYTES>>>();

    dim3 go(D / BN, MTOT / BM);        // (6, 64)
    out_gemm<<<go, 256>>>(OW_w, OW_b, out);
}

// round 12
// speedup vs baseline: 1.1055x; 1.1055x over previous
#include <cuda_runtime.h>
#include <math.h>
#include <stdint.h>

typedef unsigned long long u64;

// Problem constants
constexpr int D     = 768;
constexpr int SQ    = 2048;
constexpr int BATCH = 4;
constexpr int NH    = 12;
constexpr int HDIM  = 64;
constexpr int MTOT  = BATCH * SQ;   // 8192 rows

// Scratch (alloc-free rule: __device__ globals)
__device__ float g_Q[MTOT * D];
__device__ float g_K[MTOT * D];
__device__ float g_V[MTOT * D];
__device__ float g_ctx[MTOT * D];

// ---- packed f32x2 helpers (GEMMs only — measured 1.32x win there) --------
__device__ __forceinline__ u64 splat2(float x) {
    u64 r; unsigned xi = __float_as_uint(x);
    asm("mov.b64 %0, {%1, %1};" : "=l"(r) : "r"(xi));
    return r;
}
__device__ __forceinline__ void ffma2(u64 &d, u64 a, u64 b) {
    asm("fma.rn.f32x2 %0, %1, %2, %0;" : "+l"(d) : "l"(a), "l"(b));
}
__device__ __forceinline__ float2 unpack2(u64 v) {
    float2 f;
    asm("mov.b64 {%0, %1}, %2;" : "=f"(f.x), "=f"(f.y) : "l"(v));
    return f;
}
__device__ __forceinline__ u64 dtou(double d) { return __double_as_longlong(d); }

// ---------------------------------------------------------------------------
// GEMM (FFMA2, measured): C[m][n] = sum_k A[m][k]*W[n][k] + bias[n]
// BM=BN=128, BK=16, 256 threads, 8 rows (4 pairs) x 8 cols per thread.
// ---------------------------------------------------------------------------
constexpr int BM = 128, BN = 128, BK = 16, BMP = 132;

__device__ __forceinline__ void gemm_nt(const float* __restrict__ A,
                                        const float* __restrict__ W,
                                        const float* __restrict__ bias,
                                        float* __restrict__ C) {
    __shared__ __align__(16) float As[BK][BMP];   // [k][m]
    __shared__ __align__(16) float Bs[BK][BMP];   // [k][n]
    const int tid = threadIdx.x;
    const int tx = tid & 15, ty = tid >> 4;
    const int m0 = blockIdx.y * BM, n0 = blockIdx.x * BN;
    const int lm = tid >> 1;          // 0..127
    const int lk = (tid & 1) * 8;     // 0 or 8
    const float* Ap = A + (size_t)(m0 + lm) * D + lk;
    const float* Wp = W + (size_t)(n0 + lm) * D + lk;

    u64 acc[4][8];
#pragma unroll
    for (int i = 0; i < 4; i++)
#pragma unroll
        for (int j = 0; j < 8; j++) acc[i][j] = 0ull;

    float4 ra0 = *(const float4*)(Ap);
    float4 ra1 = *(const float4*)(Ap + 4);
    float4 rb0 = *(const float4*)(Wp);
    float4 rb1 = *(const float4*)(Wp + 4);

    for (int kt = 0; kt < D; kt += BK) {
        As[lk + 0][lm] = ra0.x; As[lk + 1][lm] = ra0.y;
        As[lk + 2][lm] = ra0.z; As[lk + 3][lm] = ra0.w;
        As[lk + 4][lm] = ra1.x; As[lk + 5][lm] = ra1.y;
        As[lk + 6][lm] = ra1.z; As[lk + 7][lm] = ra1.w;
        Bs[lk + 0][lm] = rb0.x; Bs[lk + 1][lm] = rb0.y;
        Bs[lk + 2][lm] = rb0.z; Bs[lk + 3][lm] = rb0.w;
        Bs[lk + 4][lm] = rb1.x; Bs[lk + 5][lm] = rb1.y;
        Bs[lk + 6][lm] = rb1.z; Bs[lk + 7][lm] = rb1.w;
        __syncthreads();
        if (kt + BK < D) {   // prefetch next tile
            ra0 = *(const float4*)(Ap + kt + BK);
            ra1 = *(const float4*)(Ap + kt + BK + 4);
            rb0 = *(const float4*)(Wp + kt + BK);
            rb1 = *(const float4*)(Wp + kt + BK + 4);
        }
#pragma unroll
        for (int kk = 0; kk < BK; kk++) {
            double2 A0 = *(const double2*)&As[kk][ty * 8];
            double2 A1 = *(const double2*)&As[kk][ty * 8 + 4];
            float4 B0 = *(const float4*)&Bs[kk][tx * 4];
            float4 B1 = *(const float4*)&Bs[kk][64 + tx * 4];
            u64 a[4] = {dtou(A0.x), dtou(A0.y), dtou(A1.x), dtou(A1.y)};
            u64 b[8] = {splat2(B0.x), splat2(B0.y), splat2(B0.z), splat2(B0.w),
                        splat2(B1.x), splat2(B1.y), splat2(B1.z), splat2(B1.w)};
#pragma unroll
            for (int i = 0; i < 4; i++)
#pragma unroll
                for (int j = 0; j < 8; j++)
                    ffma2(acc[i][j], a[i], b[j]);
        }
        __syncthreads();
    }

    float bb[8];
#pragma unroll
    for (int j = 0; j < 4; j++) bb[j] = bias[n0 + tx * 4 + j];
#pragma unroll
    for (int j = 0; j < 4; j++) bb[4 + j] = bias[n0 + 64 + tx * 4 + j];

#pragma unroll
    for (int i2 = 0; i2 < 4; i2++) {
        float lo[8], hi[8];
#pragma unroll
        for (int j = 0; j < 8; j++) {
            float2 v = unpack2(acc[i2][j]);
            lo[j] = v.x + bb[j];
            hi[j] = v.y + bb[j];
        }
        float* r0 = C + (size_t)(m0 + ty * 8 + 2 * i2) * D + n0;
        float* r1 = r0 + D;
        *(float4*)(r0 + tx * 4)      = make_float4(lo[0], lo[1], lo[2], lo[3]);
        *(float4*)(r0 + 64 + tx * 4) = make_float4(lo[4], lo[5], lo[6], lo[7]);
        *(float4*)(r1 + tx * 4)      = make_float4(hi[0], hi[1], hi[2], hi[3]);
        *(float4*)(r1 + 64 + tx * 4) = make_float4(hi[4], hi[5], hi[6], hi[7]);
    }
}

__global__ void __launch_bounds__(256, 2)
qkv_gemm(const float* __restrict__ x,
         const float* __restrict__ Wq, const float* __restrict__ bq,
         const float* __restrict__ Wk, const float* __restrict__ bk,
         const float* __restrict__ Wv, const float* __restrict__ bv) {
    const float* W; const float* bias; float* C;
    if (blockIdx.z == 0)      { W = Wq; bias = bq; C = g_Q; }
    else if (blockIdx.z == 1) { W = Wk; bias = bk; C = g_K; }
    else                      { W = Wv; bias = bv; C = g_V; }
    gemm_nt(x, W, bias, C);
}

__global__ void __launch_bounds__(256, 2)
out_gemm(const float* __restrict__ Wo, const float* __restrict__ bo,
         float* __restrict__ out) {
    gemm_nt(g_ctx, Wo, bo, out);
}

// ---------------------------------------------------------------------------
// Flash attention, scalar fp32 (measured-best math path) with softmax fused
// into Phase A registers. grid (16 q-tiles, 48 bh), 256 threads.
// 128 q-rows/block, 64 kv/iter, 8 rows x 4 cols per thread in BOTH phases
// (row = ty*8+i spans tx lanes 0..15 of one warp-half -> shuffle reductions).
// ---------------------------------------------------------------------------
constexpr int QP = 132;
constexpr int KP = 68;
constexpr int SP = 68;
constexpr int ATTN_SMEM_FLOATS = 64 * QP + 64 * KP + 64 * KP + 128 * SP + 256;
constexpr int ATTN_SMEM_BYTES  = ATTN_SMEM_FLOATS * 4;   // 104448 B

__global__ void __launch_bounds__(256)
attn_kernel() {
    extern __shared__ __align__(16) float sm[];
    float* Qs = sm;                    // [d][r] d-major
    float* Ks = Qs + 64 * QP;          // [d][c] d-major
    float* Vs = Ks + 64 * KP;          // [j][d] row-major
    float* Ps = Vs + 64 * KP;          // [r][c] probabilities
    float* l_s = Ps + 128 * SP;        // [128]

    const int tid = threadIdx.x;
    const int tx = tid & 15, ty = tid >> 4;
    const int bh = blockIdx.y;
    const int b = bh / NH, h = bh % NH;
    const int q0 = blockIdx.x * 128;

    const float* Qb = g_Q + (size_t)(b * SQ) * D + h * HDIM;
    const float* Kb = g_K + (size_t)(b * SQ) * D + h * HDIM;
    const float* Vb = g_V + (size_t)(b * SQ) * D + h * HDIM;

    // Load Q tile (128 x 64) transposed to d-major, scale 1/8 folded in
    {
        const int lr = tid >> 1;
        const int ld0 = (tid & 1) * 32;
        const float* qrow = Qb + (size_t)(q0 + lr) * D + ld0;
#pragma unroll
        for (int i4 = 0; i4 < 8; i4++) {
            float4 v = *(const float4*)(qrow + i4 * 4);
            int d = ld0 + i4 * 4;
            Qs[(d + 0) * QP + lr] = v.x * 0.125f;
            Qs[(d + 1) * QP + lr] = v.y * 0.125f;
            Qs[(d + 2) * QP + lr] = v.z * 0.125f;
            Qs[(d + 3) * QP + lr] = v.w * 0.125f;
        }
    }

    // Per-row online-softmax state, replicated across the 16 tx lanes
    float m_team[8], l_team[8];
#pragma unroll
    for (int i = 0; i < 8; i++) { m_team[i] = -INFINITY; l_team[i] = 0.0f; }
    float acc[8][4] = {};
    __syncthreads();

    for (int kt = 0; kt < SQ; kt += 64) {
        // Load K (d-major) and V (row-major): 64 rows x 64 d
        {
            const int lr = tid >> 2;
            const int ld0 = (tid & 3) * 16;
            const float* krow = Kb + (size_t)(kt + lr) * D + ld0;
            const float* vrow = Vb + (size_t)(kt + lr) * D + ld0;
#pragma unroll
            for (int i4 = 0; i4 < 4; i4++) {
                float4 kv = *(const float4*)(krow + i4 * 4);
                int d = ld0 + i4 * 4;
                Ks[(d + 0) * KP + lr] = kv.x;
                Ks[(d + 1) * KP + lr] = kv.y;
                Ks[(d + 2) * KP + lr] = kv.z;
                Ks[(d + 3) * KP + lr] = kv.w;
                float4 vv = *(const float4*)(vrow + i4 * 4);
                *(float4*)&Vs[lr * KP + ld0 + i4 * 4] = vv;
            }
        }
        __syncthreads();

        // Phase A + softmax fused: S in registers, row-reduce via shuffles
        float alpha_r[8];
        {
            float s[8][4] = {};
#pragma unroll
            for (int d = 0; d < 64; d++) {
                float a[8];
                float4 t;
                t = *(const float4*)&Qs[d * QP + ty * 8];     a[0]=t.x; a[1]=t.y; a[2]=t.z; a[3]=t.w;
                t = *(const float4*)&Qs[d * QP + ty * 8 + 4]; a[4]=t.x; a[5]=t.y; a[6]=t.z; a[7]=t.w;
                float4 kv = *(const float4*)&Ks[d * KP + tx * 4];
#pragma unroll
                for (int i = 0; i < 8; i++) {
                    s[i][0] = fmaf(a[i], kv.x, s[i][0]);
                    s[i][1] = fmaf(a[i], kv.y, s[i][1]);
                    s[i][2] = fmaf(a[i], kv.z, s[i][2]);
                    s[i][3] = fmaf(a[i], kv.w, s[i][3]);
                }
            }
            // Row-wise online softmax in registers (reduce over 16 tx lanes)
#pragma unroll
            for (int i = 0; i < 8; i++) {
                float mloc = fmaxf(fmaxf(s[i][0], s[i][1]),
                                   fmaxf(s[i][2], s[i][3]));
                mloc = fmaxf(mloc, __shfl_xor_sync(0xffffffffu, mloc, 1));
                mloc = fmaxf(mloc, __shfl_xor_sync(0xffffffffu, mloc, 2));
                mloc = fmaxf(mloc, __shfl_xor_sync(0xffffffffu, mloc, 4));
                mloc = fmaxf(mloc, __shfl_xor_sync(0xffffffffu, mloc, 8));
                float m_new = fmaxf(m_team[i], mloc);
                float alpha = __expf(m_team[i] - m_new);
                s[i][0] = __expf(s[i][0] - m_new);
                s[i][1] = __expf(s[i][1] - m_new);
                s[i][2] = __expf(s[i][2] - m_new);
                s[i][3] = __expf(s[i][3] - m_new);
                float lsum = (s[i][0] + s[i][1]) + (s[i][2] + s[i][3]);
                lsum += __shfl_xor_sync(0xffffffffu, lsum, 1);
                lsum += __shfl_xor_sync(0xffffffffu, lsum, 2);
                lsum += __shfl_xor_sync(0xffffffffu, lsum, 4);
                lsum += __shfl_xor_sync(0xffffffffu, lsum, 8);
                l_team[i] = l_team[i] * alpha + lsum;
                m_team[i] = m_new;
                alpha_r[i] = alpha;
                *(float4*)&Ps[(ty * 8 + i) * SP + tx * 4] =
                    make_float4(s[i][0], s[i][1], s[i][2], s[i][3]);
            }
        }
        __syncthreads();

        // Phase C: O = O*alpha + P @ V  (8x4 register accumulator, same rows)
        {
#pragma unroll
            for (int i = 0; i < 8; i++) {
                float al = alpha_r[i];
                acc[i][0] *= al; acc[i][1] *= al;
                acc[i][2] *= al; acc[i][3] *= al;
            }
#pragma unroll
            for (int j = 0; j < 64; j++) {
                float4 v = *(const float4*)&Vs[j * KP + tx * 4];
#pragma unroll
                for (int i = 0; i < 8; i++) {
                    float pp = Ps[(ty * 8 + i) * SP + j];
                    acc[i][0] = fmaf(pp, v.x, acc[i][0]);
                    acc[i][1] = fmaf(pp, v.y, acc[i][1]);
                    acc[i][2] = fmaf(pp, v.z, acc[i][2]);
                    acc[i][3] = fmaf(pp, v.w, acc[i][3]);
                }
            }
        }
        __syncthreads();   // protect Ks/Vs/Ps for next tile
    }

    // Final normalize + store ([b,s,h*64+d] layout for the O-projection).
    // l_team is replicated across tx lanes; lane tx==0's value is used.
    if (tx == 0) {
#pragma unroll
        for (int i = 0; i < 8; i++) l_s[ty * 8 + i] = l_team[i];
    }
    __syncthreads();
    float* Ob = g_ctx + (size_t)(b * SQ + q0) * D + h * HDIM;
#pragma unroll
    for (int i = 0; i < 8; i++) {
        float inv = 1.0f / l_s[ty * 8 + i];
        *(float4*)&Ob[(size_t)(ty * 8 + i) * D + tx * 4] =
            make_float4(acc[i][0] * inv, acc[i][1] * inv,
                        acc[i][2] * inv, acc[i][3] * inv);
    }
}

// ---------------------------------------------------------------------------
extern "C" void kernel_launch(void* const* d_in, const int* in_sizes, int n_in,
                              void* d_out, int out_size) {
    const float* x    = (const float*)d_in[0];
    const float* QW_w = (const float*)d_in[1];
    const float* QW_b = (const float*)d_in[2];
    const float* KW_w = (const float*)d_in[3];
    const float* KW_b = (const float*)d_in[4];
    const float* VW_w = (const float*)d_in[5];
    const float* VW_b = (const float*)d_in[6];
    const float* OW_w = (const float*)d_in[7];
    const float* OW_b = (const float*)d_in[8];
    float* out = (float*)d_out;

    cudaFuncSetAttribute(attn_kernel,
                         cudaFuncAttributeMaxDynamicSharedMemorySize,
                         ATTN_SMEM_BYTES);

    dim3 gq(D / BN, MTOT / BM, 3);     // (6, 64, 3)
    qkv_gemm<<<gq, 256>>>(x, QW_w, QW_b, KW_w, KW_b, VW_w, VW_b);

    dim3 ga(SQ / 128, BATCH * NH);     // (16, 48)
    attn_kernel<<<ga, 256, ATTN_SMEM_BYTES>>>();

    dim3 go(D / BN, MTOT / BM);        // (6, 64)
    out_gemm<<<go, 256>>>(OW_w, OW_b, out);
}

// round 14
// speedup vs baseline: 2.5050x; 2.2659x over previous
#include <cuda_runtime.h>
#include <cuda_bf16.h>
#include <math.h>
#include <stdint.h>

// Problem constants
constexpr int D     = 768;
constexpr int SQ    = 2048;
constexpr int BATCH = 4;
constexpr int NH    = 12;
constexpr int HDIM  = 64;
constexpr int MTOT  = BATCH * SQ;   // 8192

// Scratch (alloc-free rule: __device__ globals)
__device__ float g_Q[MTOT * D];
__device__ float g_K[MTOT * D];
__device__ float g_V[MTOT * D];
__device__ float g_ctx[MTOT * D];

// ===========================================================================
// Helpers: mma.sync m16n8k16 bf16 (base ISA, sm_80+), ldmatrix, bf16 split
// ===========================================================================
__device__ __forceinline__ uint32_t smem_u32(const void* p) {
    uint32_t a;
    asm("{ .reg .u64 t; cvta.to.shared.u64 t, %1; cvt.u32.u64 %0, t; }"
        : "=r"(a) : "l"(p));
    return a;
}
__device__ __forceinline__ void mma16816(float* d, const uint32_t* a,
                                         const uint32_t* b) {
    asm volatile(
        "mma.sync.aligned.m16n8k16.row.col.f32.bf16.bf16.f32 "
        "{%0,%1,%2,%3}, {%4,%5,%6,%7}, {%8,%9}, {%0,%1,%2,%3};\n"
        : "+f"(d[0]), "+f"(d[1]), "+f"(d[2]), "+f"(d[3])
        : "r"(a[0]), "r"(a[1]), "r"(a[2]), "r"(a[3]), "r"(b[0]), "r"(b[1]));
}
__device__ __forceinline__ void ldsm_x4(uint32_t* r, uint32_t addr) {
    asm volatile("ldmatrix.sync.aligned.m8n8.x4.shared.b16 {%0,%1,%2,%3}, [%4];"
                 : "=r"(r[0]), "=r"(r[1]), "=r"(r[2]), "=r"(r[3]) : "r"(addr));
}
__device__ __forceinline__ void ldsm_x2(uint32_t* r, uint32_t addr) {
    asm volatile("ldmatrix.sync.aligned.m8n8.x2.shared.b16 {%0,%1}, [%2];"
                 : "=r"(r[0]), "=r"(r[1]) : "r"(addr));
}
__device__ __forceinline__ void ldsm_x2t(uint32_t* r, uint32_t addr) {
    asm volatile("ldmatrix.sync.aligned.m8n8.x2.trans.shared.b16 {%0,%1}, [%2];"
                 : "=r"(r[0]), "=r"(r[1]) : "r"(addr));
}
// split (x,y) fp32 -> packed bf16x2 hi + bf16x2 lo residual
__device__ __forceinline__ void split2(float x, float y,
                                       uint32_t& h, uint32_t& l) {
    __nv_bfloat162 hp = __float22bfloat162_rn(make_float2(x, y));
    float2 hf = __bfloat1622float2(hp);
    __nv_bfloat162 lp = __float22bfloat162_rn(make_float2(x - hf.x, y - hf.y));
    h = *(uint32_t*)&hp;
    l = *(uint32_t*)&lp;
}

// ===========================================================================
// Projection GEMM on HMMA: C[m][n] = sum_k A[m][k]*W[n][k] + bias[n]
// 128x128 block, 8 warps (2m x 4n), each warp 64x32. BK=32 bf16.
// 3-term split: Ah*Bh + Ah*Bl + Al*Bh, fp32 accum.
// smem rows: 32 + 8 pad = 40 bf16 (80 B) — conflict-free for ldmatrix.
// ===========================================================================
constexpr int G_AH = 0, G_AL = 10240, G_BH = 20480, G_BL = 30720;

__device__ __forceinline__ void gemm_tc(const float* __restrict__ A,
                                        const float* __restrict__ W,
                                        const float* __restrict__ bias,
                                        float* __restrict__ C) {
    __shared__ __align__(16) char gsm[40960];
    const uint32_t sb = smem_u32(gsm);
    const int tid = threadIdx.x;
    const int lane = tid & 31, w = tid >> 5;
    const int wm = (w & 1) * 64, wn = (w >> 1) * 32;
    const int m0 = blockIdx.y * 128, n0 = blockIdx.x * 128;
    const int lrow = tid >> 1, lk = (tid & 1) * 16;

    float acc[4][4][4];
#pragma unroll
    for (int i = 0; i < 4; i++)
#pragma unroll
        for (int j = 0; j < 4; j++)
#pragma unroll
            for (int r = 0; r < 4; r++) acc[i][j][r] = 0.0f;

    const float* Ap = A + (size_t)(m0 + lrow) * D + lk;
    const float* Wp = W + (size_t)(n0 + lrow) * D + lk;
    char* sA = gsm + lrow * 80 + lk * 2;
    char* sB = sA;   // same intra-tile offset, different base region

    for (int kt = 0; kt < D; kt += 32) {
        {   // load + split A (16 floats) and W (16 floats) per thread
            uint32_t hh[8], ll[8];
            const float* ap = Ap + kt;
            float4 v0 = *(const float4*)(ap);
            float4 v1 = *(const float4*)(ap + 4);
            float4 v2 = *(const float4*)(ap + 8);
            float4 v3 = *(const float4*)(ap + 12);
            split2(v0.x, v0.y, hh[0], ll[0]); split2(v0.z, v0.w, hh[1], ll[1]);
            split2(v1.x, v1.y, hh[2], ll[2]); split2(v1.z, v1.w, hh[3], ll[3]);
            split2(v2.x, v2.y, hh[4], ll[4]); split2(v2.z, v2.w, hh[5], ll[5]);
            split2(v3.x, v3.y, hh[6], ll[6]); split2(v3.z, v3.w, hh[7], ll[7]);
            *(uint4*)(sA + G_AH)      = make_uint4(hh[0], hh[1], hh[2], hh[3]);
            *(uint4*)(sA + G_AH + 16) = make_uint4(hh[4], hh[5], hh[6], hh[7]);
            *(uint4*)(sA + G_AL)      = make_uint4(ll[0], ll[1], ll[2], ll[3]);
            *(uint4*)(sA + G_AL + 16) = make_uint4(ll[4], ll[5], ll[6], ll[7]);
            const float* wp = Wp + kt;
            v0 = *(const float4*)(wp);
            v1 = *(const float4*)(wp + 4);
            v2 = *(const float4*)(wp + 8);
            v3 = *(const float4*)(wp + 12);
            split2(v0.x, v0.y, hh[0], ll[0]); split2(v0.z, v0.w, hh[1], ll[1]);
            split2(v1.x, v1.y, hh[2], ll[2]); split2(v1.z, v1.w, hh[3], ll[3]);
            split2(v2.x, v2.y, hh[4], ll[4]); split2(v2.z, v2.w, hh[5], ll[5]);
            split2(v3.x, v3.y, hh[6], ll[6]); split2(v3.z, v3.w, hh[7], ll[7]);
            *(uint4*)(sB + G_BH)      = make_uint4(hh[0], hh[1], hh[2], hh[3]);
            *(uint4*)(sB + G_BH + 16) = make_uint4(hh[4], hh[5], hh[6], hh[7]);
            *(uint4*)(sB + G_BL)      = make_uint4(ll[0], ll[1], ll[2], ll[3]);
            *(uint4*)(sB + G_BL + 16) = make_uint4(ll[4], ll[5], ll[6], ll[7]);
        }
        __syncthreads();
#pragma unroll
        for (int g = 0; g < 2; g++) {
            const uint32_t kofA = (g * 16 + 8 * (lane >> 4)) * 2;
            const uint32_t kofB = (g * 16 + 8 * ((lane >> 3) & 1)) * 2;
            uint32_t bh[4][2], bl[4][2];
#pragma unroll
            for (int nf = 0; nf < 4; nf++) {
                uint32_t ba = sb + G_BH + (wn + nf * 8 + (lane & 7)) * 80 + kofB;
                ldsm_x2(bh[nf], ba);
                ldsm_x2(bl[nf], ba + 10240);
            }
#pragma unroll
            for (int mf = 0; mf < 4; mf++) {
                uint32_t aa = sb + G_AH + (wm + mf * 16 + (lane & 15)) * 80 + kofA;
                uint32_t ah[4], al[4];
                ldsm_x4(ah, aa);
                ldsm_x4(al, aa + 10240);
#pragma unroll
                for (int nf = 0; nf < 4; nf++) {
                    mma16816(acc[mf][nf], ah, bh[nf]);
                    mma16816(acc[mf][nf], ah, bl[nf]);
                    mma16816(acc[mf][nf], al, bh[nf]);
                }
            }
        }
        __syncthreads();
    }

    const int cb = n0 + wn + (lane & 3) * 2;
#pragma unroll
    for (int nf = 0; nf < 4; nf++) {
        int col = cb + nf * 8;
        float b0 = bias[col], b1 = bias[col + 1];
#pragma unroll
        for (int mf = 0; mf < 4; mf++) {
            int r0 = m0 + wm + mf * 16 + (lane >> 2);
            *(float2*)&C[(size_t)r0 * D + col] =
                make_float2(acc[mf][nf][0] + b0, acc[mf][nf][1] + b1);
            *(float2*)&C[(size_t)(r0 + 8) * D + col] =
                make_float2(acc[mf][nf][2] + b0, acc[mf][nf][3] + b1);
        }
    }
}

__global__ void __launch_bounds__(256, 2)
qkv_tc(const float* __restrict__ x,
       const float* __restrict__ Wq, const float* __restrict__ bq,
       const float* __restrict__ Wk, const float* __restrict__ bk,
       const float* __restrict__ Wv, const float* __restrict__ bv) {
    const float* W; const float* bias; float* C;
    if (blockIdx.z == 0)      { W = Wq; bias = bq; C = g_Q; }
    else if (blockIdx.z == 1) { W = Wk; bias = bk; C = g_K; }
    else                      { W = Wv; bias = bv; C = g_V; }
    gemm_tc(x, W, bias, C);
}

__global__ void __launch_bounds__(256, 2)
out_tc(const float* __restrict__ Wo, const float* __restrict__ bo,
       float* __restrict__ out) {
    gemm_tc(g_ctx, Wo, bo, out);
}

// ===========================================================================
// Flash attention on HMMA. grid (16 q-tiles, 48 bh), 256 threads (8 warps).
// Warp owns 16 q-rows. kv tile 64. hd 64. bf16 split 3-term both matmuls.
// smem rows: 64 + 8 pad = 72 bf16 (144 B) — conflict-free for ldmatrix.
// ===========================================================================
constexpr int A_QH = 0,     A_QL = 18432;
constexpr int A_KH = 36864, A_KL = 46080;
constexpr int A_VH = 55296, A_VL = 64512;
constexpr int ATTN_SMEM = 73728;

__global__ void __launch_bounds__(256)
attn_tc() {
    extern __shared__ __align__(16) char smc[];
    const uint32_t sb = smem_u32(smc);
    const int tid = threadIdx.x;
    const int lane = tid & 31, w = tid >> 5;
    const int w16 = w * 16;
    const int bh = blockIdx.y;
    const int b = bh / NH, h = bh % NH;
    const int q0 = blockIdx.x * 128;

    const float* Qb = g_Q + (size_t)(b * SQ) * D + h * HDIM;
    const float* Kb = g_K + (size_t)(b * SQ) * D + h * HDIM;
    const float* Vb = g_V + (size_t)(b * SQ) * D + h * HDIM;

    // Load Q tile (128x64), scale 1/8 folded, split to bf16 hi/lo
    {
        const int row = tid >> 1, qk = (tid & 1) * 32;
        const float* qp = Qb + (size_t)(q0 + row) * D + qk;
        char* dst = smc + row * 144 + qk * 2;
        uint32_t hh[16], ll[16];
#pragma unroll
        for (int j = 0; j < 8; j++) {
            float4 v = *(const float4*)(qp + j * 4);
            split2(v.x * 0.125f, v.y * 0.125f, hh[2 * j], ll[2 * j]);
            split2(v.z * 0.125f, v.w * 0.125f, hh[2 * j + 1], ll[2 * j + 1]);
        }
#pragma unroll
        for (int j = 0; j < 4; j++) {
            *(uint4*)(dst + A_QH + j * 16) =
                make_uint4(hh[4 * j], hh[4 * j + 1], hh[4 * j + 2], hh[4 * j + 3]);
            *(uint4*)(dst + A_QL + j * 16) =
                make_uint4(ll[4 * j], ll[4 * j + 1], ll[4 * j + 2], ll[4 * j + 3]);
        }
    }

    float o[8][4];
#pragma unroll
    for (int nf = 0; nf < 8; nf++)
#pragma unroll
        for (int r = 0; r < 4; r++) o[nf][r] = 0.0f;
    float mtA = -INFINITY, mtB = -INFINITY, ltA = 0.0f, ltB = 0.0f;
    __syncthreads();

    for (int kt = 0; kt < SQ; kt += 64) {
        // Load K, V tiles (64x64 each), split to bf16 hi/lo
        {
            const int row = tid >> 2, kk = (tid & 3) * 16;
            const float* kp = Kb + (size_t)(kt + row) * D + kk;
            const float* vp = Vb + (size_t)(kt + row) * D + kk;
            char* dst = smc + row * 144 + kk * 2;
            uint32_t hh[8], ll[8];
            float4 v0 = *(const float4*)(kp);
            float4 v1 = *(const float4*)(kp + 4);
            float4 v2 = *(const float4*)(kp + 8);
            float4 v3 = *(const float4*)(kp + 12);
            split2(v0.x, v0.y, hh[0], ll[0]); split2(v0.z, v0.w, hh[1], ll[1]);
            split2(v1.x, v1.y, hh[2], ll[2]); split2(v1.z, v1.w, hh[3], ll[3]);
            split2(v2.x, v2.y, hh[4], ll[4]); split2(v2.z, v2.w, hh[5], ll[5]);
            split2(v3.x, v3.y, hh[6], ll[6]); split2(v3.z, v3.w, hh[7], ll[7]);
            *(uint4*)(dst + A_KH)      = make_uint4(hh[0], hh[1], hh[2], hh[3]);
            *(uint4*)(dst + A_KH + 16) = make_uint4(hh[4], hh[5], hh[6], hh[7]);
            *(uint4*)(dst + A_KL)      = make_uint4(ll[0], ll[1], ll[2], ll[3]);
            *(uint4*)(dst + A_KL + 16) = make_uint4(ll[4], ll[5], ll[6], ll[7]);
            v0 = *(const float4*)(vp);
            v1 = *(const float4*)(vp + 4);
            v2 = *(const float4*)(vp + 8);
            v3 = *(const float4*)(vp + 12);
            split2(v0.x, v0.y, hh[0], ll[0]); split2(v0.z, v0.w, hh[1], ll[1]);
            split2(v1.x, v1.y, hh[2], ll[2]); split2(v1.z, v1.w, hh[3], ll[3]);
            split2(v2.x, v2.y, hh[4], ll[4]); split2(v2.z, v2.w, hh[5], ll[5]);
            split2(v3.x, v3.y, hh[6], ll[6]); split2(v3.z, v3.w, hh[7], ll[7]);
            *(uint4*)(dst + A_VH)      = make_uint4(hh[0], hh[1], hh[2], hh[3]);
            *(uint4*)(dst + A_VH + 16) = make_uint4(hh[4], hh[5], hh[6], hh[7]);
            *(uint4*)(dst + A_VL)      = make_uint4(ll[0], ll[1], ll[2], ll[3]);
            *(uint4*)(dst + A_VL + 16) = make_uint4(ll[4], ll[5], ll[6], ll[7]);
        }
        __syncthreads();

        // S = Q @ K^T (16 rows x 64 cols per warp), 3-term split
        float s[8][4];
#pragma unroll
        for (int nf = 0; nf < 8; nf++)
#pragma unroll
            for (int r = 0; r < 4; r++) s[nf][r] = 0.0f;
#pragma unroll
        for (int g = 0; g < 4; g++) {
            uint32_t qa = sb + A_QH + (w16 + (lane & 15)) * 144 +
                          (g * 16 + 8 * (lane >> 4)) * 2;
            uint32_t qh[4], ql[4];
            ldsm_x4(qh, qa);
            ldsm_x4(ql, qa + A_QL);
#pragma unroll
            for (int nf = 0; nf < 8; nf++) {
                uint32_t ka = sb + A_KH + (nf * 8 + (lane & 7)) * 144 +
                              (g * 16 + 8 * ((lane >> 3) & 1)) * 2;
                uint32_t kh2[2], kl2[2];
                ldsm_x2(kh2, ka);
                ldsm_x2(kl2, ka + 9216);
                mma16816(s[nf], qh, kh2);
                mma16816(s[nf], qh, kl2);
                mma16816(s[nf], ql, kh2);
            }
        }

        // Online softmax on fragments: rows lane/4 (A) and lane/4+8 (B)
        float mA = -INFINITY, mB = -INFINITY;
#pragma unroll
        for (int nf = 0; nf < 8; nf++) {
            mA = fmaxf(mA, fmaxf(s[nf][0], s[nf][1]));
            mB = fmaxf(mB, fmaxf(s[nf][2], s[nf][3]));
        }
        mA = fmaxf(mA, __shfl_xor_sync(0xffffffffu, mA, 1));
        mA = fmaxf(mA, __shfl_xor_sync(0xffffffffu, mA, 2));
        mB = fmaxf(mB, __shfl_xor_sync(0xffffffffu, mB, 1));
        mB = fmaxf(mB, __shfl_xor_sync(0xffffffffu, mB, 2));
        float mnA = fmaxf(mtA, mA), mnB = fmaxf(mtB, mB);
        float aA = __expf(mtA - mnA), aB = __expf(mtB - mnB);
        mtA = mnA; mtB = mnB;
        float lA = 0.0f, lB = 0.0f;
#pragma unroll
        for (int nf = 0; nf < 8; nf++) {
            s[nf][0] = __expf(s[nf][0] - mnA);
            s[nf][1] = __expf(s[nf][1] - mnA);
            s[nf][2] = __expf(s[nf][2] - mnB);
            s[nf][3] = __expf(s[nf][3] - mnB);
            lA += s[nf][0] + s[nf][1];
            lB += s[nf][2] + s[nf][3];
        }
        lA += __shfl_xor_sync(0xffffffffu, lA, 1);
        lA += __shfl_xor_sync(0xffffffffu, lA, 2);
        lB += __shfl_xor_sync(0xffffffffu, lB, 1);
        lB += __shfl_xor_sync(0xffffffffu, lB, 2);
        ltA = ltA * aA + lA;
        ltB = ltB * aB + lB;

        // O = O*alpha + P @ V. P A-fragments come straight from s[] regs.
#pragma unroll
        for (int nf = 0; nf < 8; nf++) {
            o[nf][0] *= aA; o[nf][1] *= aA;
            o[nf][2] *= aB; o[nf][3] *= aB;
        }
#pragma unroll
        for (int g = 0; g < 4; g++) {
            uint32_t ph[4], pl[4];
            split2(s[2 * g][0],     s[2 * g][1],     ph[0], pl[0]);
            split2(s[2 * g][2],     s[2 * g][3],     ph[1], pl[1]);
            split2(s[2 * g + 1][0], s[2 * g + 1][1], ph[2], pl[2]);
            split2(s[2 * g + 1][2], s[2 * g + 1][3], ph[3], pl[3]);
#pragma unroll
            for (int nf = 0; nf < 8; nf++) {
                uint32_t va = sb + A_VH + (g * 16 + (lane & 15)) * 144 + nf * 16;
                uint32_t vh2[2], vl2[2];
                ldsm_x2t(vh2, va);
                ldsm_x2t(vl2, va + 9216);
                mma16816(o[nf], ph, vh2);
                mma16816(o[nf], ph, vl2);
                mma16816(o[nf], pl, vh2);
            }
        }
        __syncthreads();   // K/V/... reused next iteration
    }

    // Normalize + store ([b,s,h*64+d] layout for the O-projection)
    float iA = 1.0f / ltA, iB = 1.0f / ltB;
    const int rA = q0 + w16 + (lane >> 2);
    float* Ob = g_ctx + (size_t)(b * SQ) * D + h * HDIM;
#pragma unroll
    for (int nf = 0; nf < 8; nf++) {
        int col = nf * 8 + (lane & 3) * 2;
        *(float2*)&Ob[(size_t)rA * D + col] =
            make_float2(o[nf][0] * iA, o[nf][1] * iA);
        *(float2*)&Ob[(size_t)(rA + 8) * D + col] =
            make_float2(o[nf][2] * iB, o[nf][3] * iB);
    }
}

// ===========================================================================
extern "C" void kernel_launch(void* const* d_in, const int* in_sizes, int n_in,
                              void* d_out, int out_size) {
    const float* x    = (const float*)d_in[0];
    const float* QW_w = (const float*)d_in[1];
    const float* QW_b = (const float*)d_in[2];
    const float* KW_w = (const float*)d_in[3];
    const float* KW_b = (const float*)d_in[4];
    const float* VW_w = (const float*)d_in[5];
    const float* VW_b = (const float*)d_in[6];
    const float* OW_w = (const float*)d_in[7];
    const float* OW_b = (const float*)d_in[8];
    float* out = (float*)d_out;

    cudaFuncSetAttribute(attn_tc,
                         cudaFuncAttributeMaxDynamicSharedMemorySize,
                         ATTN_SMEM);

    dim3 gq(D / 128, MTOT / 128, 3);   // (6, 64, 3)
    qkv_tc<<<gq, 256>>>(x, QW_w, QW_b, KW_w, KW_b, VW_w, VW_b);

    dim3 ga(SQ / 128, BATCH * NH);     // (16, 48)
    attn_tc<<<ga, 256, ATTN_SMEM>>>();

    dim3 go(D / 128, MTOT / 128);      // (6, 64)
    out_tc<<<go, 256>>>(OW_w, OW_b, out);
}

// round 15
// speedup vs baseline: 2.5737x; 1.0274x over previous
#include <cuda_runtime.h>
#include <cuda_bf16.h>
#include <math.h>
#include <stdint.h>

// Problem constants
constexpr int D     = 768;
constexpr int SQ    = 2048;
constexpr int BATCH = 4;
constexpr int NH    = 12;
constexpr int HDIM  = 64;
constexpr int MTOT  = BATCH * SQ;   // 8192

// Pre-split bf16 hi/lo scratch (alloc-free rule: __device__ globals)
__device__ uint16_t g_xh[MTOT * D],  g_xl[MTOT * D];
__device__ uint16_t g_Wh[4 * D * D], g_Wl[4 * D * D];   // Q,K,V,O
__device__ uint16_t g_Qh[MTOT * D],  g_Ql[MTOT * D];
__device__ uint16_t g_Kh[MTOT * D],  g_Kl[MTOT * D];
__device__ uint16_t g_Vh[MTOT * D],  g_Vl[MTOT * D];
__device__ uint16_t g_ch[MTOT * D],  g_cl[MTOT * D];

// ===========================================================================
// Helpers
// ===========================================================================
__device__ __forceinline__ uint32_t smem_u32(const void* p) {
    uint32_t a;
    asm("{ .reg .u64 t; cvta.to.shared.u64 t, %1; cvt.u32.u64 %0, t; }"
        : "=r"(a) : "l"(p));
    return a;
}
__device__ __forceinline__ void mma16816(float* d, const uint32_t* a,
                                         const uint32_t* b) {
    asm volatile(
        "mma.sync.aligned.m16n8k16.row.col.f32.bf16.bf16.f32 "
        "{%0,%1,%2,%3}, {%4,%5,%6,%7}, {%8,%9}, {%0,%1,%2,%3};\n"
        : "+f"(d[0]), "+f"(d[1]), "+f"(d[2]), "+f"(d[3])
        : "r"(a[0]), "r"(a[1]), "r"(a[2]), "r"(a[3]), "r"(b[0]), "r"(b[1]));
}
__device__ __forceinline__ void ldsm_x4(uint32_t* r, uint32_t addr) {
    asm volatile("ldmatrix.sync.aligned.m8n8.x4.shared.b16 {%0,%1,%2,%3}, [%4];"
                 : "=r"(r[0]), "=r"(r[1]), "=r"(r[2]), "=r"(r[3]) : "r"(addr));
}
__device__ __forceinline__ void ldsm_x2(uint32_t* r, uint32_t addr) {
    asm volatile("ldmatrix.sync.aligned.m8n8.x2.shared.b16 {%0,%1}, [%2];"
                 : "=r"(r[0]), "=r"(r[1]) : "r"(addr));
}
__device__ __forceinline__ void ldsm_x2t(uint32_t* r, uint32_t addr) {
    asm volatile("ldmatrix.sync.aligned.m8n8.x2.trans.shared.b16 {%0,%1}, [%2];"
                 : "=r"(r[0]), "=r"(r[1]) : "r"(addr));
}
// split (x,y) fp32 -> packed bf16x2 hi + bf16x2 lo residual
__device__ __forceinline__ void split2(float x, float y,
                                       uint32_t& h, uint32_t& l) {
    __nv_bfloat162 hp = __float22bfloat162_rn(make_float2(x, y));
    float2 hf = __bfloat1622float2(hp);
    __nv_bfloat162 lp = __float22bfloat162_rn(make_float2(x - hf.x, y - hf.y));
    h = *(uint32_t*)&hp;
    l = *(uint32_t*)&lp;
}

// ===========================================================================
// Pre-convert: fp32 -> hi/lo bf16 arrays
// ===========================================================================
__global__ void __launch_bounds__(256)
conv_split(const float* __restrict__ src, uint16_t* __restrict__ h,
           uint16_t* __restrict__ l, int n4) {
    int i = blockIdx.x * 256 + threadIdx.x;
    if (i < n4) {
        float4 v = ((const float4*)src)[i];
        uint32_t h0, l0, h1, l1;
        split2(v.x, v.y, h0, l0);
        split2(v.z, v.w, h1, l1);
        ((uint2*)h)[i] = make_uint2(h0, h1);
        ((uint2*)l)[i] = make_uint2(l0, l1);
    }
}

// ===========================================================================
// HMMA GEMM, bf16 hi/lo inputs: C = A @ B^T + bias  (3-term split accumulate)
// 128x128 block, 8 warps (2m x 4n), warp tile 64x32, BK=32.
// smem rows: 32 bf16 + 8 pad = 80 B. Layout identical to R14 (proven).
// SPLITOUT: write hi/lo bf16 (optionally scaled); else fp32.
// ===========================================================================
constexpr int G_AH = 0, G_AL = 10240, G_BH = 20480, G_BL = 30720;

template <bool SPLITOUT>
__device__ __forceinline__ void gemm_tc(const uint16_t* __restrict__ Ahg,
                                        const uint16_t* __restrict__ Alg,
                                        const uint16_t* __restrict__ Bhg,
                                        const uint16_t* __restrict__ Blg,
                                        const float* __restrict__ bias,
                                        float scale,
                                        float* __restrict__ Cf,
                                        uint16_t* __restrict__ Ch,
                                        uint16_t* __restrict__ Cl) {
    __shared__ __align__(16) char gsm[40960];
    const uint32_t sb = smem_u32(gsm);
    const int tid = threadIdx.x;
    const int lane = tid & 31, w = tid >> 5;
    const int wm = (w & 1) * 64, wn = (w >> 1) * 32;
    const int m0 = blockIdx.y * 128, n0 = blockIdx.x * 128;
    const int lrow = tid >> 1, lk = (tid & 1) * 16;

    float acc[4][4][4];
#pragma unroll
    for (int i = 0; i < 4; i++)
#pragma unroll
        for (int j = 0; j < 4; j++)
#pragma unroll
            for (int r = 0; r < 4; r++) acc[i][j][r] = 0.0f;

    const uint16_t* Ah = Ahg + (size_t)(m0 + lrow) * D + lk;
    const uint16_t* Al = Alg + (size_t)(m0 + lrow) * D + lk;
    const uint16_t* Bh = Bhg + (size_t)(n0 + lrow) * D + lk;
    const uint16_t* Bl = Blg + (size_t)(n0 + lrow) * D + lk;
    char* sd = gsm + lrow * 80 + lk * 2;

    for (int kt = 0; kt < D; kt += 32) {
        *(uint4*)(sd + G_AH)      = *(const uint4*)(Ah + kt);
        *(uint4*)(sd + G_AH + 16) = *(const uint4*)(Ah + kt + 8);
        *(uint4*)(sd + G_AL)      = *(const uint4*)(Al + kt);
        *(uint4*)(sd + G_AL + 16) = *(const uint4*)(Al + kt + 8);
        *(uint4*)(sd + G_BH)      = *(const uint4*)(Bh + kt);
        *(uint4*)(sd + G_BH + 16) = *(const uint4*)(Bh + kt + 8);
        *(uint4*)(sd + G_BL)      = *(const uint4*)(Bl + kt);
        *(uint4*)(sd + G_BL + 16) = *(const uint4*)(Bl + kt + 8);
        __syncthreads();
#pragma unroll
        for (int g = 0; g < 2; g++) {
            const uint32_t kofA = (g * 16 + 8 * (lane >> 4)) * 2;
            const uint32_t kofB = (g * 16 + 8 * ((lane >> 3) & 1)) * 2;
            uint32_t bh[4][2], bl[4][2];
#pragma unroll
            for (int nf = 0; nf < 4; nf++) {
                uint32_t ba = sb + G_BH + (wn + nf * 8 + (lane & 7)) * 80 + kofB;
                ldsm_x2(bh[nf], ba);
                ldsm_x2(bl[nf], ba + 10240);
            }
#pragma unroll
            for (int mf = 0; mf < 4; mf++) {
                uint32_t aa = sb + G_AH + (wm + mf * 16 + (lane & 15)) * 80 + kofA;
                uint32_t ah[4], al[4];
                ldsm_x4(ah, aa);
                ldsm_x4(al, aa + 10240);
#pragma unroll
                for (int nf = 0; nf < 4; nf++) {
                    mma16816(acc[mf][nf], ah, bh[nf]);
                    mma16816(acc[mf][nf], ah, bl[nf]);
                    mma16816(acc[mf][nf], al, bh[nf]);
                }
            }
        }
        __syncthreads();
    }

    const int cb = n0 + wn + (lane & 3) * 2;
#pragma unroll
    for (int nf = 0; nf < 4; nf++) {
        int col = cb + nf * 8;
        float b0 = bias[col], b1 = bias[col + 1];
#pragma unroll
        for (int mf = 0; mf < 4; mf++) {
            size_t r0 = (size_t)(m0 + wm + mf * 16 + (lane >> 2)) * D + col;
            size_t r1 = r0 + (size_t)8 * D;
            if (SPLITOUT) {
                uint32_t h0, l0, h1, l1;
                split2((acc[mf][nf][0] + b0) * scale,
                       (acc[mf][nf][1] + b1) * scale, h0, l0);
                split2((acc[mf][nf][2] + b0) * scale,
                       (acc[mf][nf][3] + b1) * scale, h1, l1);
                *(uint32_t*)&Ch[r0] = h0;
                *(uint32_t*)&Cl[r0] = l0;
                *(uint32_t*)&Ch[r1] = h1;
                *(uint32_t*)&Cl[r1] = l1;
            } else {
                *(float2*)&Cf[r0] =
                    make_float2(acc[mf][nf][0] + b0, acc[mf][nf][1] + b1);
                *(float2*)&Cf[r1] =
                    make_float2(acc[mf][nf][2] + b0, acc[mf][nf][3] + b1);
            }
        }
    }
}

__global__ void __launch_bounds__(256, 2)
qkv_tc(const float* __restrict__ bq, const float* __restrict__ bk,
       const float* __restrict__ bv) {
    const int z = blockIdx.z;
    const float* bias; uint16_t* Ch; uint16_t* Cl; float scale;
    if (z == 0)      { bias = bq; Ch = g_Qh; Cl = g_Ql; scale = 0.125f; }
    else if (z == 1) { bias = bk; Ch = g_Kh; Cl = g_Kl; scale = 1.0f; }
    else             { bias = bv; Ch = g_Vh; Cl = g_Vl; scale = 1.0f; }
    gemm_tc<true>(g_xh, g_xl, g_Wh + (size_t)z * D * D, g_Wl + (size_t)z * D * D,
                  bias, scale, nullptr, Ch, Cl);
}

__global__ void __launch_bounds__(256, 2)
out_tc(const float* __restrict__ bo, float* __restrict__ out) {
    gemm_tc<false>(g_ch, g_cl, g_Wh + (size_t)3 * D * D, g_Wl + (size_t)3 * D * D,
                   bo, 1.0f, out, nullptr, nullptr);
}

// ===========================================================================
// Flash attention on HMMA, bf16 hi/lo inputs. grid (16, 48), 8 warps.
// Warp owns 16 q-rows; kv tile 64; hd 64. Layout identical to R14 (proven).
// smem rows: 64 bf16 + 8 pad = 144 B.
// ===========================================================================
constexpr int A_QH = 0,     A_QL = 18432;
constexpr int A_KH = 36864, A_KL = 46080;
constexpr int A_VH = 55296, A_VL = 64512;
constexpr int ATTN_SMEM = 73728;

__global__ void __launch_bounds__(256)
attn_tc() {
    extern __shared__ __align__(16) char smc[];
    const uint32_t sb = smem_u32(smc);
    const int tid = threadIdx.x;
    const int lane = tid & 31, w = tid >> 5;
    const int w16 = w * 16;
    const int bh = blockIdx.y;
    const int b = bh / NH, h = bh % NH;
    const int q0 = blockIdx.x * 128;

    const size_t base = (size_t)(b * SQ) * D + h * HDIM;
    const uint16_t* Qhb = g_Qh + base;
    const uint16_t* Qlb = g_Ql + base;
    const uint16_t* Khb = g_Kh + base;
    const uint16_t* Klb = g_Kl + base;
    const uint16_t* Vhb = g_Vh + base;
    const uint16_t* Vlb = g_Vl + base;

    // Load Q tile (128x64 bf16 hi/lo) — straight uint4 copies
    {
        const int row = tid >> 1, qk = (tid & 1) * 32;
        const uint16_t* qh = Qhb + (size_t)(q0 + row) * D + qk;
        const uint16_t* ql = Qlb + (size_t)(q0 + row) * D + qk;
        char* dst = smc + row * 144 + qk * 2;
#pragma unroll
        for (int j = 0; j < 4; j++) {
            *(uint4*)(dst + A_QH + j * 16) = ((const uint4*)qh)[j];
            *(uint4*)(dst + A_QL + j * 16) = ((const uint4*)ql)[j];
        }
    }

    float o[8][4];
#pragma unroll
    for (int nf = 0; nf < 8; nf++)
#pragma unroll
        for (int r = 0; r < 4; r++) o[nf][r] = 0.0f;
    float mtA = -INFINITY, mtB = -INFINITY, ltA = 0.0f, ltB = 0.0f;
    __syncthreads();

    for (int kt = 0; kt < SQ; kt += 64) {
        // Load K, V tiles (64x64 bf16 hi/lo each) — straight uint4 copies
        {
            const int row = tid >> 2, kk = (tid & 3) * 16;
            const size_t off = (size_t)(kt + row) * D + kk;
            char* dst = smc + row * 144 + kk * 2;
            const uint4* kh = (const uint4*)(Khb + off);
            const uint4* kl = (const uint4*)(Klb + off);
            const uint4* vh = (const uint4*)(Vhb + off);
            const uint4* vl = (const uint4*)(Vlb + off);
            *(uint4*)(dst + A_KH)      = kh[0];
            *(uint4*)(dst + A_KH + 16) = kh[1];
            *(uint4*)(dst + A_KL)      = kl[0];
            *(uint4*)(dst + A_KL + 16) = kl[1];
            *(uint4*)(dst + A_VH)      = vh[0];
            *(uint4*)(dst + A_VH + 16) = vh[1];
            *(uint4*)(dst + A_VL)      = vl[0];
            *(uint4*)(dst + A_VL + 16) = vl[1];
        }
        __syncthreads();

        // S = Q @ K^T (16 rows x 64 cols per warp), 3-term split
        float s[8][4];
#pragma unroll
        for (int nf = 0; nf < 8; nf++)
#pragma unroll
            for (int r = 0; r < 4; r++) s[nf][r] = 0.0f;
#pragma unroll
        for (int g = 0; g < 4; g++) {
            uint32_t qa = sb + A_QH + (w16 + (lane & 15)) * 144 +
                          (g * 16 + 8 * (lane >> 4)) * 2;
            uint32_t qh[4], ql[4];
            ldsm_x4(qh, qa);
            ldsm_x4(ql, qa + A_QL);
#pragma unroll
            for (int nf = 0; nf < 8; nf++) {
                uint32_t ka = sb + A_KH + (nf * 8 + (lane & 7)) * 144 +
                              (g * 16 + 8 * ((lane >> 3) & 1)) * 2;
                uint32_t kh2[2], kl2[2];
                ldsm_x2(kh2, ka);
                ldsm_x2(kl2, ka + 9216);
                mma16816(s[nf], qh, kh2);
                mma16816(s[nf], qh, kl2);
                mma16816(s[nf], ql, kh2);
            }
        }

        // Online softmax on fragments (rows lane/4 and lane/4+8)
        float mA = -INFINITY, mB = -INFINITY;
#pragma unroll
        for (int nf = 0; nf < 8; nf++) {
            mA = fmaxf(mA, fmaxf(s[nf][0], s[nf][1]));
            mB = fmaxf(mB, fmaxf(s[nf][2], s[nf][3]));
        }
        mA = fmaxf(mA, __shfl_xor_sync(0xffffffffu, mA, 1));
        mA = fmaxf(mA, __shfl_xor_sync(0xffffffffu, mA, 2));
        mB = fmaxf(mB, __shfl_xor_sync(0xffffffffu, mB, 1));
        mB = fmaxf(mB, __shfl_xor_sync(0xffffffffu, mB, 2));
        float mnA = fmaxf(mtA, mA), mnB = fmaxf(mtB, mB);
        float aA = __expf(mtA - mnA), aB = __expf(mtB - mnB);
        mtA = mnA; mtB = mnB;
        float lA = 0.0f, lB = 0.0f;
#pragma unroll
        for (int nf = 0; nf < 8; nf++) {
            s[nf][0] = __expf(s[nf][0] - mnA);
            s[nf][1] = __expf(s[nf][1] - mnA);
            s[nf][2] = __expf(s[nf][2] - mnB);
            s[nf][3] = __expf(s[nf][3] - mnB);
            lA += s[nf][0] + s[nf][1];
            lB += s[nf][2] + s[nf][3];
        }
        lA += __shfl_xor_sync(0xffffffffu, lA, 1);
        lA += __shfl_xor_sync(0xffffffffu, lA, 2);
        lB += __shfl_xor_sync(0xffffffffu, lB, 1);
        lB += __shfl_xor_sync(0xffffffffu, lB, 2);
        ltA = ltA * aA + lA;
        ltB = ltB * aB + lB;

        // O = O*alpha + P @ V. P A-fragments straight from s[] registers.
#pragma unroll
        for (int nf = 0; nf < 8; nf++) {
            o[nf][0] *= aA; o[nf][1] *= aA;
            o[nf][2] *= aB; o[nf][3] *= aB;
        }
#pragma unroll
        for (int g = 0; g < 4; g++) {
            uint32_t ph[4], pl[4];
            split2(s[2 * g][0],     s[2 * g][1],     ph[0], pl[0]);
            split2(s[2 * g][2],     s[2 * g][3],     ph[1], pl[1]);
            split2(s[2 * g + 1][0], s[2 * g + 1][1], ph[2], pl[2]);
            split2(s[2 * g + 1][2], s[2 * g + 1][3], ph[3], pl[3]);
#pragma unroll
            for (int nf = 0; nf < 8; nf++) {
                uint32_t va = sb + A_VH + (g * 16 + (lane & 15)) * 144 + nf * 16;
                uint32_t vh2[2], vl2[2];
                ldsm_x2t(vh2, va);
                ldsm_x2t(vl2, va + 9216);
                mma16816(o[nf], ph, vh2);
                mma16816(o[nf], ph, vl2);
                mma16816(o[nf], pl, vh2);
            }
        }
        __syncthreads();   // K/V reused next iteration
    }

    // Normalize + store ctx as hi/lo bf16 ([b,s,h*64+d] layout)
    float iA = 1.0f / ltA, iB = 1.0f / ltB;
    const int rA = q0 + w16 + (lane >> 2);
    uint16_t* chb = g_ch + base;
    uint16_t* clb = g_cl + base;
#pragma unroll
    for (int nf = 0; nf < 8; nf++) {
        int col = nf * 8 + (lane & 3) * 2;
        size_t r0 = (size_t)rA * D + col;
        size_t r1 = r0 + (size_t)8 * D;
        uint32_t h0, l0, h1, l1;
        split2(o[nf][0] * iA, o[nf][1] * iA, h0, l0);
        split2(o[nf][2] * iB, o[nf][3] * iB, h1, l1);
        *(uint32_t*)&chb[r0] = h0;
        *(uint32_t*)&clb[r0] = l0;
        *(uint32_t*)&chb[r1] = h1;
        *(uint32_t*)&clb[r1] = l1;
    }
}

// ===========================================================================
extern "C" void kernel_launch(void* const* d_in, const int* in_sizes, int n_in,
                              void* d_out, int out_size) {
    const float* x    = (const float*)d_in[0];
    const float* QW_w = (const float*)d_in[1];
    const float* QW_b = (const float*)d_in[2];
    const float* KW_w = (const float*)d_in[3];
    const float* KW_b = (const float*)d_in[4];
    const float* VW_w = (const float*)d_in[5];
    const float* VW_b = (const float*)d_in[6];
    const float* OW_w = (const float*)d_in[7];
    const float* OW_b = (const float*)d_in[8];
    float* out = (float*)d_out;

    cudaFuncSetAttribute(attn_tc,
                         cudaFuncAttributeMaxDynamicSharedMemorySize,
                         ATTN_SMEM);

    // Resolve device-global scratch addresses (host side, capture-safe)
    static uint16_t *xh = nullptr, *xl, *wh, *wl;
    if (!xh) {
        cudaGetSymbolAddress((void**)&xh, g_xh);
        cudaGetSymbolAddress((void**)&xl, g_xl);
        cudaGetSymbolAddress((void**)&wh, g_Wh);
        cudaGetSymbolAddress((void**)&wl, g_Wl);
    }

    // Pre-split x and the four weight matrices into hi/lo bf16
    const int nX4 = MTOT * D / 4;          // 1,572,864
    const int nW4 = D * D / 4;             // 147,456
    conv_split<<<(nX4 + 255) / 256, 256>>>(x, xh, xl, nX4);
    conv_split<<<(nW4 + 255) / 256, 256>>>(QW_w, wh,             wl,             nW4);
    conv_split<<<(nW4 + 255) / 256, 256>>>(KW_w, wh + D * D,     wl + D * D,     nW4);
    conv_split<<<(nW4 + 255) / 256, 256>>>(VW_w, wh + 2 * D * D, wl + 2 * D * D, nW4);
    conv_split<<<(nW4 + 255) / 256, 256>>>(OW_w, wh + 3 * D * D, wl + 3 * D * D, nW4);

    dim3 gq(D / 128, MTOT / 128, 3);   // (6, 64, 3)
    qkv_tc<<<gq, 256>>>(QW_b, KW_b, VW_b);

    dim3 ga(SQ / 128, BATCH * NH);     // (16, 48)
    attn_tc<<<ga, 256, ATTN_SMEM>>>();

    dim3 go(D / 128, MTOT / 128);      // (6, 64)
    out_tc<<<go, 256>>>(OW_b, out);
}

// round 16
// speedup vs baseline: 2.6740x; 1.0390x over previous
#include <cuda_runtime.h>
#include <cuda_bf16.h>
#include <math.h>
#include <stdint.h>

// Problem constants
constexpr int D     = 768;
constexpr int SQ    = 2048;
constexpr int BATCH = 4;
constexpr int NH    = 12;
constexpr int HDIM  = 64;
constexpr int MTOT  = BATCH * SQ;   // 8192

// Pre-split bf16 hi/lo scratch (alloc-free rule: __device__ globals)
__device__ uint16_t g_xh[MTOT * D],  g_xl[MTOT * D];
__device__ uint16_t g_Wh[4 * D * D], g_Wl[4 * D * D];   // Q,K,V,O
__device__ uint16_t g_Qh[MTOT * D],  g_Ql[MTOT * D];
__device__ uint16_t g_Kh[MTOT * D],  g_Kl[MTOT * D];
__device__ uint16_t g_Vh[MTOT * D],  g_Vl[MTOT * D];
__device__ uint16_t g_ch[MTOT * D],  g_cl[MTOT * D];

// ===========================================================================
// Helpers
// ===========================================================================
__device__ __forceinline__ uint32_t smem_u32(const void* p) {
    uint32_t a;
    asm("{ .reg .u64 t; cvta.to.shared.u64 t, %1; cvt.u32.u64 %0, t; }"
        : "=r"(a) : "l"(p));
    return a;
}
__device__ __forceinline__ void mma16816(float* d, const uint32_t* a,
                                         const uint32_t* b) {
    asm volatile(
        "mma.sync.aligned.m16n8k16.row.col.f32.bf16.bf16.f32 "
        "{%0,%1,%2,%3}, {%4,%5,%6,%7}, {%8,%9}, {%0,%1,%2,%3};\n"
        : "+f"(d[0]), "+f"(d[1]), "+f"(d[2]), "+f"(d[3])
        : "r"(a[0]), "r"(a[1]), "r"(a[2]), "r"(a[3]), "r"(b[0]), "r"(b[1]));
}
__device__ __forceinline__ void ldsm_x4(uint32_t* r, uint32_t addr) {
    asm volatile("ldmatrix.sync.aligned.m8n8.x4.shared.b16 {%0,%1,%2,%3}, [%4];"
                 : "=r"(r[0]), "=r"(r[1]), "=r"(r[2]), "=r"(r[3]) : "r"(addr));
}
__device__ __forceinline__ void ldsm_x4t(uint32_t* r, uint32_t addr) {
    asm volatile("ldmatrix.sync.aligned.m8n8.x4.trans.shared.b16 {%0,%1,%2,%3}, [%4];"
                 : "=r"(r[0]), "=r"(r[1]), "=r"(r[2]), "=r"(r[3]) : "r"(addr));
}
__device__ __forceinline__ void cp16(uint32_t dst, const void* src) {
    asm volatile("cp.async.cg.shared.global [%0], [%1], 16;"
                 :: "r"(dst), "l"(src));
}
__device__ __forceinline__ void cp_commit() {
    asm volatile("cp.async.commit_group;" ::: "memory");
}
__device__ __forceinline__ void cp_wait1() {
    asm volatile("cp.async.wait_group 1;" ::: "memory");
}
__device__ __forceinline__ void cp_wait0() {
    asm volatile("cp.async.wait_group 0;" ::: "memory");
}
// split (x,y) fp32 -> packed bf16x2 hi + bf16x2 lo residual
__device__ __forceinline__ void split2(float x, float y,
                                       uint32_t& h, uint32_t& l) {
    __nv_bfloat162 hp = __float22bfloat162_rn(make_float2(x, y));
    float2 hf = __bfloat1622float2(hp);
    __nv_bfloat162 lp = __float22bfloat162_rn(make_float2(x - hf.x, y - hf.y));
    h = *(uint32_t*)&hp;
    l = *(uint32_t*)&lp;
}

// ===========================================================================
// Pre-convert: fp32 -> hi/lo bf16 arrays
// ===========================================================================
__global__ void __launch_bounds__(256)
conv_split(const float* __restrict__ src, uint16_t* __restrict__ h,
           uint16_t* __restrict__ l, int n4) {
    int i = blockIdx.x * 256 + threadIdx.x;
    if (i < n4) {
        float4 v = ((const float4*)src)[i];
        uint32_t h0, l0, h1, l1;
        split2(v.x, v.y, h0, l0);
        split2(v.z, v.w, h1, l1);
        ((uint2*)h)[i] = make_uint2(h0, h1);
        ((uint2*)l)[i] = make_uint2(l0, l1);
    }
}

// ===========================================================================
// HMMA GEMM, bf16 hi/lo inputs, cp.async double-buffered.
// C = A @ B^T + bias, 3-term split. 128x128 block, 8 warps (2m x 4n),
// warp tile 64x32, BK=32. Stage = 40960 B (rows 80 B). 2 stages dynamic.
// ===========================================================================
constexpr int G_AH = 0, G_AL = 10240, G_BH = 20480, G_BL = 30720;
constexpr int G_STAGE = 40960;
constexpr int G_SMEM  = 2 * G_STAGE;
constexpr int G_NIT   = D / 32;   // 24

template <bool SPLITOUT>
__device__ __forceinline__ void gemm_tc(const uint16_t* __restrict__ Ahg,
                                        const uint16_t* __restrict__ Alg,
                                        const uint16_t* __restrict__ Bhg,
                                        const uint16_t* __restrict__ Blg,
                                        const float* __restrict__ bias,
                                        float scale,
                                        float* __restrict__ Cf,
                                        uint16_t* __restrict__ Ch,
                                        uint16_t* __restrict__ Cl) {
    extern __shared__ __align__(16) char gsm[];
    const uint32_t sb = smem_u32(gsm);
    const int tid = threadIdx.x;
    const int lane = tid & 31, w = tid >> 5;
    const int wm = (w & 1) * 64, wn = (w >> 1) * 32;
    const int m0 = blockIdx.y * 128, n0 = blockIdx.x * 128;
    const int lrow = tid >> 1, lk = (tid & 1) * 16;

    float acc[4][4][4];
#pragma unroll
    for (int i = 0; i < 4; i++)
#pragma unroll
        for (int j = 0; j < 4; j++)
#pragma unroll
            for (int r = 0; r < 4; r++) acc[i][j][r] = 0.0f;

    const uint16_t* Ah = Ahg + (size_t)(m0 + lrow) * D + lk;
    const uint16_t* Al = Alg + (size_t)(m0 + lrow) * D + lk;
    const uint16_t* Bh = Bhg + (size_t)(n0 + lrow) * D + lk;
    const uint16_t* Bl = Blg + (size_t)(n0 + lrow) * D + lk;
    const uint32_t sd = sb + lrow * 80 + lk * 2;

    auto issue = [&](int stage, int kt) {
        uint32_t d0 = sd + stage * G_STAGE;
        cp16(d0 + G_AH,      Ah + kt);
        cp16(d0 + G_AH + 16, Ah + kt + 8);
        cp16(d0 + G_AL,      Al + kt);
        cp16(d0 + G_AL + 16, Al + kt + 8);
        cp16(d0 + G_BH,      Bh + kt);
        cp16(d0 + G_BH + 16, Bh + kt + 8);
        cp16(d0 + G_BL,      Bl + kt);
        cp16(d0 + G_BL + 16, Bl + kt + 8);
        cp_commit();
    };

    issue(0, 0);
    for (int it = 0; it < G_NIT; it++) {
        if (it + 1 < G_NIT) { issue((it + 1) & 1, (it + 1) * 32); cp_wait1(); }
        else                { cp_wait0(); }
        __syncthreads();
        const uint32_t st = sb + (it & 1) * G_STAGE;
#pragma unroll
        for (int g = 0; g < 2; g++) {
            const uint32_t kofA = (g * 16 + 8 * (lane >> 4)) * 2;
            const uint32_t kofB = (g * 16 + 8 * ((lane >> 3) & 1)) * 2;
            uint32_t bh[2][4], bl[2][4];
#pragma unroll
            for (int nfp = 0; nfp < 2; nfp++) {
                uint32_t ba = st + G_BH +
                    (wn + nfp * 16 + (lane >> 4) * 8 + (lane & 7)) * 80 + kofB;
                ldsm_x4(bh[nfp], ba);
                ldsm_x4(bl[nfp], ba + 10240);
            }
#pragma unroll
            for (int mf = 0; mf < 4; mf++) {
                uint32_t aa = st + G_AH + (wm + mf * 16 + (lane & 15)) * 80 + kofA;
                uint32_t ah[4], al[4];
                ldsm_x4(ah, aa);
                ldsm_x4(al, aa + 10240);
#pragma unroll
                for (int nf = 0; nf < 4; nf++) {
                    const uint32_t* bhp = &bh[nf >> 1][(nf & 1) * 2];
                    const uint32_t* blp = &bl[nf >> 1][(nf & 1) * 2];
                    mma16816(acc[mf][nf], ah, bhp);
                    mma16816(acc[mf][nf], ah, blp);
                    mma16816(acc[mf][nf], al, bhp);
                }
            }
        }
        __syncthreads();
    }

    const int cb = n0 + wn + (lane & 3) * 2;
#pragma unroll
    for (int nf = 0; nf < 4; nf++) {
        int col = cb + nf * 8;
        float b0 = bias[col], b1 = bias[col + 1];
#pragma unroll
        for (int mf = 0; mf < 4; mf++) {
            size_t r0 = (size_t)(m0 + wm + mf * 16 + (lane >> 2)) * D + col;
            size_t r1 = r0 + (size_t)8 * D;
            if (SPLITOUT) {
                uint32_t h0, l0, h1, l1;
                split2((acc[mf][nf][0] + b0) * scale,
                       (acc[mf][nf][1] + b1) * scale, h0, l0);
                split2((acc[mf][nf][2] + b0) * scale,
                       (acc[mf][nf][3] + b1) * scale, h1, l1);
                *(uint32_t*)&Ch[r0] = h0;
                *(uint32_t*)&Cl[r0] = l0;
                *(uint32_t*)&Ch[r1] = h1;
                *(uint32_t*)&Cl[r1] = l1;
            } else {
                *(float2*)&Cf[r0] =
                    make_float2(acc[mf][nf][0] + b0, acc[mf][nf][1] + b1);
                *(float2*)&Cf[r1] =
                    make_float2(acc[mf][nf][2] + b0, acc[mf][nf][3] + b1);
            }
        }
    }
}

__global__ void __launch_bounds__(256, 2)
qkv_tc(const float* __restrict__ bq, const float* __restrict__ bk,
       const float* __restrict__ bv) {
    const int z = blockIdx.z;
    const float* bias; uint16_t* Ch; uint16_t* Cl; float scale;
    if (z == 0)      { bias = bq; Ch = g_Qh; Cl = g_Ql; scale = 0.125f; }
    else if (z == 1) { bias = bk; Ch = g_Kh; Cl = g_Kl; scale = 1.0f; }
    else             { bias = bv; Ch = g_Vh; Cl = g_Vl; scale = 1.0f; }
    gemm_tc<true>(g_xh, g_xl, g_Wh + (size_t)z * D * D, g_Wl + (size_t)z * D * D,
                  bias, scale, nullptr, Ch, Cl);
}

__global__ void __launch_bounds__(256, 2)
out_tc(const float* __restrict__ bo, float* __restrict__ out) {
    gemm_tc<false>(g_ch, g_cl, g_Wh + (size_t)3 * D * D, g_Wl + (size_t)3 * D * D,
                   bo, 1.0f, out, nullptr, nullptr);
}

// ===========================================================================
// Flash attention on HMMA, bf16 hi/lo, cp.async double-buffered KV.
// grid (16, 48), 8 warps; warp owns 16 q-rows; kv tile 64; hd 64.
// Q: rows 144 B (64 bf16 + pad). KV stage: KH/KL/VH/VL x 9216 = 36864 B.
// ===========================================================================
constexpr int A_QH = 0, A_QL = 18432;
constexpr int A_KV0 = 36864;       // stage 0 base
constexpr int A_KVST = 36864;      // stage size
constexpr int ATTN_SMEM = A_KV0 + 2 * A_KVST;   // 110592

__global__ void __launch_bounds__(256)
attn_tc() {
    extern __shared__ __align__(16) char smc[];
    const uint32_t sb = smem_u32(smc);
    const int tid = threadIdx.x;
    const int lane = tid & 31, w = tid >> 5;
    const int w16 = w * 16;
    const int bh = blockIdx.y;
    const int b = bh / NH, h = bh % NH;
    const int q0 = blockIdx.x * 128;

    const size_t base = (size_t)(b * SQ) * D + h * HDIM;
    const uint16_t* Qhb = g_Qh + base;
    const uint16_t* Qlb = g_Ql + base;
    const uint16_t* Khb = g_Kh + base;
    const uint16_t* Klb = g_Kl + base;
    const uint16_t* Vhb = g_Vh + base;
    const uint16_t* Vlb = g_Vl + base;

    // KV cp.async per-thread source/dest mapping
    const int krow = tid >> 2, kkk = (tid & 3) * 16;
    const uint32_t kvdst = sb + krow * 144 + kkk * 2;   // + region + stage

    auto issue_kv = [&](int stage, int kt) {
        const size_t off = (size_t)(kt + krow) * D + kkk;
        uint32_t d0 = kvdst + A_KV0 + stage * A_KVST;
        cp16(d0,              Khb + off);
        cp16(d0 + 16,         Khb + off + 8);
        cp16(d0 + 9216,       Klb + off);
        cp16(d0 + 9216 + 16,  Klb + off + 8);
        cp16(d0 + 18432,      Vhb + off);
        cp16(d0 + 18432 + 16, Vhb + off + 8);
        cp16(d0 + 27648,      Vlb + off);
        cp16(d0 + 27648 + 16, Vlb + off + 8);
        cp_commit();
    };

    issue_kv(0, 0);

    // Load Q tile (128x64 bf16 hi/lo) — plain vector copies (once)
    {
        const int row = tid >> 1, qk = (tid & 1) * 32;
        const uint16_t* qh = Qhb + (size_t)(q0 + row) * D + qk;
        const uint16_t* ql = Qlb + (size_t)(q0 + row) * D + qk;
        char* dst = smc + row * 144 + qk * 2;
#pragma unroll
        for (int j = 0; j < 4; j++) {
            *(uint4*)(dst + A_QH + j * 16) = ((const uint4*)qh)[j];
            *(uint4*)(dst + A_QL + j * 16) = ((const uint4*)ql)[j];
        }
    }

    float o[8][4];
#pragma unroll
    for (int nf = 0; nf < 8; nf++)
#pragma unroll
        for (int r = 0; r < 4; r++) o[nf][r] = 0.0f;
    float mtA = -INFINITY, mtB = -INFINITY, ltA = 0.0f, ltB = 0.0f;

    for (int it = 0; it < SQ / 64; it++) {
        if (it + 1 < SQ / 64) { issue_kv((it + 1) & 1, (it + 1) * 64); cp_wait1(); }
        else                  { cp_wait0(); }
        __syncthreads();
        const uint32_t kb = sb + A_KV0 + (it & 1) * A_KVST;
        const uint32_t vb = kb + 18432;

        // S = Q @ K^T (16 rows x 64 cols per warp), 3-term split
        float s[8][4];
#pragma unroll
        for (int nf = 0; nf < 8; nf++)
#pragma unroll
            for (int r = 0; r < 4; r++) s[nf][r] = 0.0f;
#pragma unroll
        for (int g = 0; g < 4; g++) {
            uint32_t qa = sb + A_QH + (w16 + (lane & 15)) * 144 +
                          (g * 16 + 8 * (lane >> 4)) * 2;
            uint32_t qh[4], ql[4];
            ldsm_x4(qh, qa);
            ldsm_x4(ql, qa + A_QL);
#pragma unroll
            for (int nfp = 0; nfp < 4; nfp++) {
                uint32_t ka = kb +
                    (nfp * 16 + (lane >> 4) * 8 + (lane & 7)) * 144 +
                    (g * 16 + 8 * ((lane >> 3) & 1)) * 2;
                uint32_t kh4[4], kl4[4];
                ldsm_x4(kh4, ka);
                ldsm_x4(kl4, ka + 9216);
                mma16816(s[2 * nfp],     qh, kh4);
                mma16816(s[2 * nfp],     qh, kl4);
                mma16816(s[2 * nfp],     ql, kh4);
                mma16816(s[2 * nfp + 1], qh, kh4 + 2);
                mma16816(s[2 * nfp + 1], qh, kl4 + 2);
                mma16816(s[2 * nfp + 1], ql, kh4 + 2);
            }
        }

        // Online softmax on fragments (rows lane/4 and lane/4+8)
        float mA = -INFINITY, mB = -INFINITY;
#pragma unroll
        for (int nf = 0; nf < 8; nf++) {
            mA = fmaxf(mA, fmaxf(s[nf][0], s[nf][1]));
            mB = fmaxf(mB, fmaxf(s[nf][2], s[nf][3]));
        }
        mA = fmaxf(mA, __shfl_xor_sync(0xffffffffu, mA, 1));
        mA = fmaxf(mA, __shfl_xor_sync(0xffffffffu, mA, 2));
        mB = fmaxf(mB, __shfl_xor_sync(0xffffffffu, mB, 1));
        mB = fmaxf(mB, __shfl_xor_sync(0xffffffffu, mB, 2));
        float mnA = fmaxf(mtA, mA), mnB = fmaxf(mtB, mB);
        float aA = __expf(mtA - mnA), aB = __expf(mtB - mnB);
        mtA = mnA; mtB = mnB;
        float lA = 0.0f, lB = 0.0f;
#pragma unroll
        for (int nf = 0; nf < 8; nf++) {
            s[nf][0] = __expf(s[nf][0] - mnA);
            s[nf][1] = __expf(s[nf][1] - mnA);
            s[nf][2] = __expf(s[nf][2] - mnB);
            s[nf][3] = __expf(s[nf][3] - mnB);
            lA += s[nf][0] + s[nf][1];
            lB += s[nf][2] + s[nf][3];
        }
        lA += __shfl_xor_sync(0xffffffffu, lA, 1);
        lA += __shfl_xor_sync(0xffffffffu, lA, 2);
        lB += __shfl_xor_sync(0xffffffffu, lB, 1);
        lB += __shfl_xor_sync(0xffffffffu, lB, 2);
        ltA = ltA * aA + lA;
        ltB = ltB * aB + lB;

        // O = O*alpha + P @ V (P A-frags straight from s[] registers)
#pragma unroll
        for (int nf = 0; nf < 8; nf++) {
            o[nf][0] *= aA; o[nf][1] *= aA;
            o[nf][2] *= aB; o[nf][3] *= aB;
        }
#pragma unroll
        for (int g = 0; g < 4; g++) {
            uint32_t ph[4], pl[4];
            split2(s[2 * g][0],     s[2 * g][1],     ph[0], pl[0]);
            split2(s[2 * g][2],     s[2 * g][3],     ph[1], pl[1]);
            split2(s[2 * g + 1][0], s[2 * g + 1][1], ph[2], pl[2]);
            split2(s[2 * g + 1][2], s[2 * g + 1][3], ph[3], pl[3]);
#pragma unroll
            for (int nfp = 0; nfp < 4; nfp++) {
                uint32_t va = vb + (g * 16 + (lane & 15)) * 144 +
                              nfp * 32 + (lane >> 4) * 16;
                uint32_t vh4[4], vl4[4];
                ldsm_x4t(vh4, va);
                ldsm_x4t(vl4, va + 9216);
                mma16816(o[2 * nfp],     ph, vh4);
                mma16816(o[2 * nfp],     ph, vl4);
                mma16816(o[2 * nfp],     pl, vh4);
                mma16816(o[2 * nfp + 1], ph, vh4 + 2);
                mma16816(o[2 * nfp + 1], ph, vl4 + 2);
                mma16816(o[2 * nfp + 1], pl, vh4 + 2);
            }
        }
        __syncthreads();   // all warps done with this KV stage
    }

    // Normalize + store ctx as hi/lo bf16 ([b,s,h*64+d] layout)
    float iA = 1.0f / ltA, iB = 1.0f / ltB;
    const int rA = q0 + w16 + (lane >> 2);
    uint16_t* chb = g_ch + base;
    uint16_t* clb = g_cl + base;
#pragma unroll
    for (int nf = 0; nf < 8; nf++) {
        int col = nf * 8 + (lane & 3) * 2;
        size_t r0 = (size_t)rA * D + col;
        size_t r1 = r0 + (size_t)8 * D;
        uint32_t h0, l0, h1, l1;
        split2(o[nf][0] * iA, o[nf][1] * iA, h0, l0);
        split2(o[nf][2] * iB, o[nf][3] * iB, h1, l1);
        *(uint32_t*)&chb[r0] = h0;
        *(uint32_t*)&clb[r0] = l0;
        *(uint32_t*)&chb[r1] = h1;
        *(uint32_t*)&clb[r1] = l1;
    }
}

// ===========================================================================
extern "C" void kernel_launch(void* const* d_in, const int* in_sizes, int n_in,
                              void* d_out, int out_size) {
    const float* x    = (const float*)d_in[0];
    const float* QW_w = (const float*)d_in[1];
    const float* QW_b = (const float*)d_in[2];
    const float* KW_w = (const float*)d_in[3];
    const float* KW_b = (const float*)d_in[4];
    const float* VW_w = (const float*)d_in[5];
    const float* VW_b = (const float*)d_in[6];
    const float* OW_w = (const float*)d_in[7];
    const float* OW_b = (const float*)d_in[8];
    float* out = (float*)d_out;

    cudaFuncSetAttribute(qkv_tc,
                         cudaFuncAttributeMaxDynamicSharedMemorySize, G_SMEM);
    cudaFuncSetAttribute(out_tc,
                         cudaFuncAttributeMaxDynamicSharedMemorySize, G_SMEM);
    cudaFuncSetAttribute(attn_tc,
                         cudaFuncAttributeMaxDynamicSharedMemorySize, ATTN_SMEM);

    // Resolve device-global scratch addresses (host side, capture-safe)
    static uint16_t *xh = nullptr, *xl, *wh, *wl;
    if (!xh) {
        cudaGetSymbolAddress((void**)&xh, g_xh);
        cudaGetSymbolAddress((void**)&xl, g_xl);
        cudaGetSymbolAddress((void**)&wh, g_Wh);
        cudaGetSymbolAddress((void**)&wl, g_Wl);
    }

    // Pre-split x and the four weight matrices into hi/lo bf16
    const int nX4 = MTOT * D / 4;
    const int nW4 = D * D / 4;
    conv_split<<<(nX4 + 255) / 256, 256>>>(x, xh, xl, nX4);
    conv_split<<<(nW4 + 255) / 256, 256>>>(QW_w, wh,             wl,             nW4);
    conv_split<<<(nW4 + 255) / 256, 256>>>(KW_w, wh + D * D,     wl + D * D,     nW4);
    conv_split<<<(nW4 + 255) / 256, 256>>>(VW_w, wh + 2 * D * D, wl + 2 * D * D, nW4);
    conv_split<<<(nW4 + 255) / 256, 256>>>(OW_w, wh + 3 * D * D, wl + 3 * D * D, nW4);

    dim3 gq(D / 128, MTOT / 128, 3);   // (6, 64, 3)
    qkv_tc<<<gq, 256, G_SMEM>>>(QW_b, KW_b, VW_b);

    dim3 ga(SQ / 128, BATCH * NH);     // (16, 48)
    attn_tc<<<ga, 256, ATTN_SMEM>>>();

    dim3 go(D / 128, MTOT / 128);      // (6, 64)
    out_tc<<<go, 256, G_SMEM>>>(OW_b, out);
}

// round 17
// speedup vs baseline: 2.7959x; 1.0456x over previous
#include <cuda_runtime.h>
#include <cuda_bf16.h>
#include <math.h>
#include <stdint.h>

// Problem constants
constexpr int D     = 768;
constexpr int SQ    = 2048;
constexpr int BATCH = 4;
constexpr int NH    = 12;
constexpr int HDIM  = 64;
constexpr int MTOT  = BATCH * SQ;   // 8192

// Pre-split bf16 hi/lo scratch (alloc-free rule: __device__ globals)
__device__ uint16_t g_xh[MTOT * D],  g_xl[MTOT * D];
__device__ uint16_t g_Wh[4 * D * D], g_Wl[4 * D * D];   // Q,K,V,O
__device__ uint16_t g_Qh[MTOT * D],  g_Ql[MTOT * D];
__device__ uint16_t g_Kh[MTOT * D],  g_Kl[MTOT * D];
__device__ uint16_t g_Vh[MTOT * D],  g_Vl[MTOT * D];
__device__ uint16_t g_ch[MTOT * D],  g_cl[MTOT * D];

// ===========================================================================
// Helpers
// ===========================================================================
__device__ __forceinline__ uint32_t smem_u32(const void* p) {
    uint32_t a;
    asm("{ .reg .u64 t; cvta.to.shared.u64 t, %1; cvt.u32.u64 %0, t; }"
        : "=r"(a) : "l"(p));
    return a;
}
__device__ __forceinline__ void mma16816(float* d, const uint32_t* a,
                                         const uint32_t* b) {
    asm volatile(
        "mma.sync.aligned.m16n8k16.row.col.f32.bf16.bf16.f32 "
        "{%0,%1,%2,%3}, {%4,%5,%6,%7}, {%8,%9}, {%0,%1,%2,%3};\n"
        : "+f"(d[0]), "+f"(d[1]), "+f"(d[2]), "+f"(d[3])
        : "r"(a[0]), "r"(a[1]), "r"(a[2]), "r"(a[3]), "r"(b[0]), "r"(b[1]));
}
__device__ __forceinline__ void ldsm_x4(uint32_t* r, uint32_t addr) {
    asm volatile("ldmatrix.sync.aligned.m8n8.x4.shared.b16 {%0,%1,%2,%3}, [%4];"
                 : "=r"(r[0]), "=r"(r[1]), "=r"(r[2]), "=r"(r[3]) : "r"(addr));
}
__device__ __forceinline__ void ldsm_x4t(uint32_t* r, uint32_t addr) {
    asm volatile("ldmatrix.sync.aligned.m8n8.x4.trans.shared.b16 {%0,%1,%2,%3}, [%4];"
                 : "=r"(r[0]), "=r"(r[1]), "=r"(r[2]), "=r"(r[3]) : "r"(addr));
}
__device__ __forceinline__ void cp16(uint32_t dst, const void* src) {
    asm volatile("cp.async.cg.shared.global [%0], [%1], 16;"
                 :: "r"(dst), "l"(src));
}
__device__ __forceinline__ void cp_commit() {
    asm volatile("cp.async.commit_group;" ::: "memory");
}
__device__ __forceinline__ void cp_wait1() {
    asm volatile("cp.async.wait_group 1;" ::: "memory");
}
__device__ __forceinline__ void cp_wait0() {
    asm volatile("cp.async.wait_group 0;" ::: "memory");
}
// split (x,y) fp32 -> packed bf16x2 hi + bf16x2 lo residual
__device__ __forceinline__ void split2(float x, float y,
                                       uint32_t& h, uint32_t& l) {
    __nv_bfloat162 hp = __float22bfloat162_rn(make_float2(x, y));
    float2 hf = __bfloat1622float2(hp);
    __nv_bfloat162 lp = __float22bfloat162_rn(make_float2(x - hf.x, y - hf.y));
    h = *(uint32_t*)&hp;
    l = *(uint32_t*)&lp;
}

// ===========================================================================
// Pre-convert: fp32 -> hi/lo bf16 arrays
// ===========================================================================
__global__ void __launch_bounds__(256)
conv_split(const float* __restrict__ src, uint16_t* __restrict__ h,
           uint16_t* __restrict__ l, int n4) {
    int i = blockIdx.x * 256 + threadIdx.x;
    if (i < n4) {
        float4 v = ((const float4*)src)[i];
        uint32_t h0, l0, h1, l1;
        split2(v.x, v.y, h0, l0);
        split2(v.z, v.w, h1, l1);
        ((uint2*)h)[i] = make_uint2(h0, h1);
        ((uint2*)l)[i] = make_uint2(l0, l1);
    }
}

// ===========================================================================
// HMMA GEMM, bf16 hi/lo inputs, cp.async double-buffered (unchanged R16).
// C = A @ B^T + bias, 3-term split. 128x128 block, 8 warps (2m x 4n),
// warp tile 64x32, BK=32. Stage = 40960 B (rows 80 B). 2 stages dynamic.
// ===========================================================================
constexpr int G_AH = 0, G_AL = 10240, G_BH = 20480, G_BL = 30720;
constexpr int G_STAGE = 40960;
constexpr int G_SMEM  = 2 * G_STAGE;
constexpr int G_NIT   = D / 32;   // 24

template <bool SPLITOUT>
__device__ __forceinline__ void gemm_tc(const uint16_t* __restrict__ Ahg,
                                        const uint16_t* __restrict__ Alg,
                                        const uint16_t* __restrict__ Bhg,
                                        const uint16_t* __restrict__ Blg,
                                        const float* __restrict__ bias,
                                        float scale,
                                        float* __restrict__ Cf,
                                        uint16_t* __restrict__ Ch,
                                        uint16_t* __restrict__ Cl) {
    extern __shared__ __align__(16) char gsm[];
    const uint32_t sb = smem_u32(gsm);
    const int tid = threadIdx.x;
    const int lane = tid & 31, w = tid >> 5;
    const int wm = (w & 1) * 64, wn = (w >> 1) * 32;
    const int m0 = blockIdx.y * 128, n0 = blockIdx.x * 128;
    const int lrow = tid >> 1, lk = (tid & 1) * 16;

    float acc[4][4][4];
#pragma unroll
    for (int i = 0; i < 4; i++)
#pragma unroll
        for (int j = 0; j < 4; j++)
#pragma unroll
            for (int r = 0; r < 4; r++) acc[i][j][r] = 0.0f;

    const uint16_t* Ah = Ahg + (size_t)(m0 + lrow) * D + lk;
    const uint16_t* Al = Alg + (size_t)(m0 + lrow) * D + lk;
    const uint16_t* Bh = Bhg + (size_t)(n0 + lrow) * D + lk;
    const uint16_t* Bl = Blg + (size_t)(n0 + lrow) * D + lk;
    const uint32_t sd = sb + lrow * 80 + lk * 2;

    auto issue = [&](int stage, int kt) {
        uint32_t d0 = sd + stage * G_STAGE;
        cp16(d0 + G_AH,      Ah + kt);
        cp16(d0 + G_AH + 16, Ah + kt + 8);
        cp16(d0 + G_AL,      Al + kt);
        cp16(d0 + G_AL + 16, Al + kt + 8);
        cp16(d0 + G_BH,      Bh + kt);
        cp16(d0 + G_BH + 16, Bh + kt + 8);
        cp16(d0 + G_BL,      Bl + kt);
        cp16(d0 + G_BL + 16, Bl + kt + 8);
        cp_commit();
    };

    issue(0, 0);
    for (int it = 0; it < G_NIT; it++) {
        if (it + 1 < G_NIT) { issue((it + 1) & 1, (it + 1) * 32); cp_wait1(); }
        else                { cp_wait0(); }
        __syncthreads();
        const uint32_t st = sb + (it & 1) * G_STAGE;
#pragma unroll
        for (int g = 0; g < 2; g++) {
            const uint32_t kofA = (g * 16 + 8 * (lane >> 4)) * 2;
            const uint32_t kofB = (g * 16 + 8 * ((lane >> 3) & 1)) * 2;
            uint32_t bh[2][4], bl[2][4];
#pragma unroll
            for (int nfp = 0; nfp < 2; nfp++) {
                uint32_t ba = st + G_BH +
                    (wn + nfp * 16 + (lane >> 4) * 8 + (lane & 7)) * 80 + kofB;
                ldsm_x4(bh[nfp], ba);
                ldsm_x4(bl[nfp], ba + 10240);
            }
#pragma unroll
            for (int mf = 0; mf < 4; mf++) {
                uint32_t aa = st + G_AH + (wm + mf * 16 + (lane & 15)) * 80 + kofA;
                uint32_t ah[4], al[4];
                ldsm_x4(ah, aa);
                ldsm_x4(al, aa + 10240);
#pragma unroll
                for (int nf = 0; nf < 4; nf++) {
                    const uint32_t* bhp = &bh[nf >> 1][(nf & 1) * 2];
                    const uint32_t* blp = &bl[nf >> 1][(nf & 1) * 2];
                    mma16816(acc[mf][nf], ah, bhp);
                    mma16816(acc[mf][nf], ah, blp);
                    mma16816(acc[mf][nf], al, bhp);
                }
            }
        }
        __syncthreads();
    }

    const int cb = n0 + wn + (lane & 3) * 2;
#pragma unroll
    for (int nf = 0; nf < 4; nf++) {
        int col = cb + nf * 8;
        float b0 = bias[col], b1 = bias[col + 1];
#pragma unroll
        for (int mf = 0; mf < 4; mf++) {
            size_t r0 = (size_t)(m0 + wm + mf * 16 + (lane >> 2)) * D + col;
            size_t r1 = r0 + (size_t)8 * D;
            if (SPLITOUT) {
                uint32_t h0, l0, h1, l1;
                split2((acc[mf][nf][0] + b0) * scale,
                       (acc[mf][nf][1] + b1) * scale, h0, l0);
                split2((acc[mf][nf][2] + b0) * scale,
                       (acc[mf][nf][3] + b1) * scale, h1, l1);
                *(uint32_t*)&Ch[r0] = h0;
                *(uint32_t*)&Cl[r0] = l0;
                *(uint32_t*)&Ch[r1] = h1;
                *(uint32_t*)&Cl[r1] = l1;
            } else {
                *(float2*)&Cf[r0] =
                    make_float2(acc[mf][nf][0] + b0, acc[mf][nf][1] + b1);
                *(float2*)&Cf[r1] =
                    make_float2(acc[mf][nf][2] + b0, acc[mf][nf][3] + b1);
            }
        }
    }
}

__global__ void __launch_bounds__(256, 2)
qkv_tc(const float* __restrict__ bq, const float* __restrict__ bk,
       const float* __restrict__ bv) {
    const int z = blockIdx.z;
    const float* bias; uint16_t* Ch; uint16_t* Cl; float scale;
    if (z == 0)      { bias = bq; Ch = g_Qh; Cl = g_Ql; scale = 0.125f; }
    else if (z == 1) { bias = bk; Ch = g_Kh; Cl = g_Kl; scale = 1.0f; }
    else             { bias = bv; Ch = g_Vh; Cl = g_Vl; scale = 1.0f; }
    gemm_tc<true>(g_xh, g_xl, g_Wh + (size_t)z * D * D, g_Wl + (size_t)z * D * D,
                  bias, scale, nullptr, Ch, Cl);
}

__global__ void __launch_bounds__(256, 2)
out_tc(const float* __restrict__ bo, float* __restrict__ out) {
    gemm_tc<false>(g_ch, g_cl, g_Wh + (size_t)3 * D * D, g_Wl + (size_t)3 * D * D,
                   bo, 1.0f, out, nullptr, nullptr);
}

// ===========================================================================
// Flash attention on HMMA, bf16 hi/lo, cp.async double-buffered KV.
// NOW: 512 threads (16 warps), 256 q-rows per CTA, grid (8, 48).
// Warp owns 16 q-rows; kv tile 64; hd 64. Rows 144 B (64 bf16 + pad).
// Q: 256 rows hi+lo = 73728 B. KV stage: KH/KL/VH/VL x 9216 = 36864 B x 2.
// ===========================================================================
constexpr int A_QH = 0, A_QL = 36864;
constexpr int A_KV0 = 73728;       // stage 0 base
constexpr int A_KVST = 36864;      // stage size
constexpr int ATTN_SMEM = A_KV0 + 2 * A_KVST;   // 147456

__global__ void __launch_bounds__(512, 1)
attn_tc() {
    extern __shared__ __align__(16) char smc[];
    const uint32_t sb = smem_u32(smc);
    const int tid = threadIdx.x;
    const int lane = tid & 31, w = tid >> 5;     // w = 0..15
    const int w16 = w * 16;                      // warp's q-row base (0..240)
    const int bh = blockIdx.y;
    const int b = bh / NH, h = bh % NH;
    const int q0 = blockIdx.x * 256;

    const size_t base = (size_t)(b * SQ) * D + h * HDIM;
    const uint16_t* Qhb = g_Qh + base;
    const uint16_t* Qlb = g_Ql + base;
    const uint16_t* Khb = g_Kh + base;
    const uint16_t* Klb = g_Kl + base;
    const uint16_t* Vhb = g_Vh + base;
    const uint16_t* Vlb = g_Vl + base;

    // KV cp.async mapping: 512 threads cover 64 rows x 8 16B-chunks
    const int krow = tid >> 3;                 // 0..63
    const int kchunk = (tid & 7) * 8;          // element offset 0..56
    const uint32_t kvdst = sb + krow * 144 + kchunk * 2;

    auto issue_kv = [&](int stage, int kt) {
        const size_t off = (size_t)(kt + krow) * D + kchunk;
        uint32_t d0 = kvdst + A_KV0 + stage * A_KVST;
        cp16(d0,         Khb + off);
        cp16(d0 + 9216,  Klb + off);
        cp16(d0 + 18432, Vhb + off);
        cp16(d0 + 27648, Vlb + off);
        cp_commit();
    };

    issue_kv(0, 0);

    // Load Q tile (256x64 bf16 hi/lo) — plain vector copies (once)
    {
        const int row = tid >> 1, qk = (tid & 1) * 32;
        const uint16_t* qh = Qhb + (size_t)(q0 + row) * D + qk;
        const uint16_t* ql = Qlb + (size_t)(q0 + row) * D + qk;
        char* dst = smc + row * 144 + qk * 2;
#pragma unroll
        for (int j = 0; j < 4; j++) {
            *(uint4*)(dst + A_QH + j * 16) = ((const uint4*)qh)[j];
            *(uint4*)(dst + A_QL + j * 16) = ((const uint4*)ql)[j];
        }
    }

    float o[8][4];
#pragma unroll
    for (int nf = 0; nf < 8; nf++)
#pragma unroll
        for (int r = 0; r < 4; r++) o[nf][r] = 0.0f;
    float mtA = -INFINITY, mtB = -INFINITY, ltA = 0.0f, ltB = 0.0f;

    for (int it = 0; it < SQ / 64; it++) {
        if (it + 1 < SQ / 64) { issue_kv((it + 1) & 1, (it + 1) * 64); cp_wait1(); }
        else                  { cp_wait0(); }
        __syncthreads();
        const uint32_t kb = sb + A_KV0 + (it & 1) * A_KVST;
        const uint32_t vb = kb + 18432;

        // S = Q @ K^T (16 rows x 64 cols per warp), 3-term split
        float s[8][4];
#pragma unroll
        for (int nf = 0; nf < 8; nf++)
#pragma unroll
            for (int r = 0; r < 4; r++) s[nf][r] = 0.0f;
#pragma unroll
        for (int g = 0; g < 4; g++) {
            uint32_t qa = sb + A_QH + (w16 + (lane & 15)) * 144 +
                          (g * 16 + 8 * (lane >> 4)) * 2;
            uint32_t qh[4], ql[4];
            ldsm_x4(qh, qa);
            ldsm_x4(ql, qa + A_QL);
#pragma unroll
            for (int nfp = 0; nfp < 4; nfp++) {
                uint32_t ka = kb +
                    (nfp * 16 + (lane >> 4) * 8 + (lane & 7)) * 144 +
                    (g * 16 + 8 * ((lane >> 3) & 1)) * 2;
                uint32_t kh4[4], kl4[4];
                ldsm_x4(kh4, ka);
                ldsm_x4(kl4, ka + 9216);
                mma16816(s[2 * nfp],     qh, kh4);
                mma16816(s[2 * nfp],     qh, kl4);
                mma16816(s[2 * nfp],     ql, kh4);
                mma16816(s[2 * nfp + 1], qh, kh4 + 2);
                mma16816(s[2 * nfp + 1], qh, kl4 + 2);
                mma16816(s[2 * nfp + 1], ql, kh4 + 2);
            }
        }

        // Online softmax on fragments (rows lane/4 and lane/4+8)
        float mA = -INFINITY, mB = -INFINITY;
#pragma unroll
        for (int nf = 0; nf < 8; nf++) {
            mA = fmaxf(mA, fmaxf(s[nf][0], s[nf][1]));
            mB = fmaxf(mB, fmaxf(s[nf][2], s[nf][3]));
        }
        mA = fmaxf(mA, __shfl_xor_sync(0xffffffffu, mA, 1));
        mA = fmaxf(mA, __shfl_xor_sync(0xffffffffu, mA, 2));
        mB = fmaxf(mB, __shfl_xor_sync(0xffffffffu, mB, 1));
        mB = fmaxf(mB, __shfl_xor_sync(0xffffffffu, mB, 2));
        float mnA = fmaxf(mtA, mA), mnB = fmaxf(mtB, mB);
        float aA = __expf(mtA - mnA), aB = __expf(mtB - mnB);
        mtA = mnA; mtB = mnB;
        float lA = 0.0f, lB = 0.0f;
#pragma unroll
        for (int nf = 0; nf < 8; nf++) {
            s[nf][0] = __expf(s[nf][0] - mnA);
            s[nf][1] = __expf(s[nf][1] - mnA);
            s[nf][2] = __expf(s[nf][2] - mnB);
            s[nf][3] = __expf(s[nf][3] - mnB);
            lA += s[nf][0] + s[nf][1];
            lB += s[nf][2] + s[nf][3];
        }
        lA += __shfl_xor_sync(0xffffffffu, lA, 1);
        lA += __shfl_xor_sync(0xffffffffu, lA, 2);
        lB += __shfl_xor_sync(0xffffffffu, lB, 1);
        lB += __shfl_xor_sync(0xffffffffu, lB, 2);
        ltA = ltA * aA + lA;
        ltB = ltB * aB + lB;

        // O = O*alpha + P @ V (P A-frags straight from s[] registers)
#pragma unroll
        for (int nf = 0; nf < 8; nf++) {
            o[nf][0] *= aA; o[nf][1] *= aA;
            o[nf][2] *= aB; o[nf][3] *= aB;
        }
#pragma unroll
        for (int g = 0; g < 4; g++) {
            uint32_t ph[4], pl[4];
            split2(s[2 * g][0],     s[2 * g][1],     ph[0], pl[0]);
            split2(s[2 * g][2],     s[2 * g][3],     ph[1], pl[1]);
            split2(s[2 * g + 1][0], s[2 * g + 1][1], ph[2], pl[2]);
            split2(s[2 * g + 1][2], s[2 * g + 1][3], ph[3], pl[3]);
#pragma unroll
            for (int nfp = 0; nfp < 4; nfp++) {
                uint32_t va = vb + (g * 16 + (lane & 15)) * 144 +
                              nfp * 32 + (lane >> 4) * 16;
                uint32_t vh4[4], vl4[4];
                ldsm_x4t(vh4, va);
                ldsm_x4t(vl4, va + 9216);
                mma16816(o[2 * nfp],     ph, vh4);
                mma16816(o[2 * nfp],     ph, vl4);
                mma16816(o[2 * nfp],     pl, vh4);
                mma16816(o[2 * nfp + 1], ph, vh4 + 2);
                mma16816(o[2 * nfp + 1], ph, vl4 + 2);
                mma16816(o[2 * nfp + 1], pl, vh4 + 2);
            }
        }
        __syncthreads();   // all warps done with this KV stage
    }

    // Normalize + store ctx as hi/lo bf16 ([b,s,h*64+d] layout)
    float iA = 1.0f / ltA, iB = 1.0f / ltB;
    const int rA = q0 + w16 + (lane >> 2);
    uint16_t* chb = g_ch + base;
    uint16_t* clb = g_cl + base;
#pragma unroll
    for (int nf = 0; nf < 8; nf++) {
        int col = nf * 8 + (lane & 3) * 2;
        size_t r0 = (size_t)rA * D + col;
        size_t r1 = r0 + (size_t)8 * D;
        uint32_t h0, l0, h1, l1;
        split2(o[nf][0] * iA, o[nf][1] * iA, h0, l0);
        split2(o[nf][2] * iB, o[nf][3] * iB, h1, l1);
        *(uint32_t*)&chb[r0] = h0;
        *(uint32_t*)&clb[r0] = l0;
        *(uint32_t*)&chb[r1] = h1;
        *(uint32_t*)&clb[r1] = l1;
    }
}

// ===========================================================================
extern "C" void kernel_launch(void* const* d_in, const int* in_sizes, int n_in,
                              void* d_out, int out_size) {
    const float* x    = (const float*)d_in[0];
    const float* QW_w = (const float*)d_in[1];
    const float* QW_b = (const float*)d_in[2];
    const float* KW_w = (const float*)d_in[3];
    const float* KW_b = (const float*)d_in[4];
    const float* VW_w = (const float*)d_in[5];
    const float* VW_b = (const float*)d_in[6];
    const float* OW_w = (const float*)d_in[7];
    const float* OW_b = (const float*)d_in[8];
    float* out = (float*)d_out;

    cudaFuncSetAttribute(qkv_tc,
                         cudaFuncAttributeMaxDynamicSharedMemorySize, G_SMEM);
    cudaFuncSetAttribute(out_tc,
                         cudaFuncAttributeMaxDynamicSharedMemorySize, G_SMEM);
    cudaFuncSetAttribute(attn_tc,
                         cudaFuncAttributeMaxDynamicSharedMemorySize, ATTN_SMEM);

    // Resolve device-global scratch addresses (host side, capture-safe)
    static uint16_t *xh = nullptr, *xl, *wh, *wl;
    if (!xh) {
        cudaGetSymbolAddress((void**)&xh, g_xh);
        cudaGetSymbolAddress((void**)&xl, g_xl);
        cudaGetSymbolAddress((void**)&wh, g_Wh);
        cudaGetSymbolAddress((void**)&wl, g_Wl);
    }

    // Pre-split x and the four weight matrices into hi/lo bf16
    const int nX4 = MTOT * D / 4;
    const int nW4 = D * D / 4;
    conv_split<<<(nX4 + 255) / 256, 256>>>(x, xh, xl, nX4);
    conv_split<<<(nW4 + 255) / 256, 256>>>(QW_w, wh,             wl,             nW4);
    conv_split<<<(nW4 + 255) / 256, 256>>>(KW_w, wh + D * D,     wl + D * D,     nW4);
    conv_split<<<(nW4 + 255) / 256, 256>>>(VW_w, wh + 2 * D * D, wl + 2 * D * D, nW4);
    conv_split<<<(nW4 + 255) / 256, 256>>>(OW_w, wh + 3 * D * D, wl + 3 * D * D, nW4);

    dim3 gq(D / 128, MTOT / 128, 3);   // (6, 64, 3)
    qkv_tc<<<gq, 256, G_SMEM>>>(QW_b, KW_b, VW_b);

    dim3 ga(SQ / 256, BATCH * NH);     // (8, 48)
    attn_tc<<<ga, 512, ATTN_SMEM>>>();

    dim3 go(D / 128, MTOT / 128);      // (6, 64)
    out_tc<<<go, 256, G_SMEM>>>(OW_b, out);
}